// round 2
// baseline (speedup 1.0000x reference)
#include <cuda_runtime.h>
#include <cuda_bf16.h>
#include <cstdint>

// Problem constants (fixed by the dataset): B=8, N=1024, K=16, D=256, L=3
#define BB 8
#define NN 1024
#define KK 16
#define DD 256
#define LL 3
#define M_TOT (BB * NN)          // 8192 rows
#define K_TOT (2 * DD)           // 512  (concat of in/out halves)
#define N_TOT (4 * DD)           // 1024 (4 gates x 256)

// ---------------- scratch (static device globals; no runtime alloc) --------
__device__ float g_Wpack[K_TOT * N_TOT];   // 2 MB
__device__ float g_Upack[K_TOT * N_TOT];   // 2 MB
__device__ float g_xw  [M_TOT * N_TOT];    // 32 MB  (layer-invariant x-part + bias)
__device__ float g_pre [M_TOT * N_TOT];    // 32 MB
__device__ float g_Hin [M_TOT * DD];       // 8 MB
__device__ float g_Hout[M_TOT * DD];       // 8 MB
__device__ float g_h   [M_TOT * DD];       // 8 MB
__device__ float g_c   [M_TOT * DD];       // 8 MB

// ---------------- weight packing -------------------------------------------
// Wpack[e][g*256+d] = (e<256) ? W_in[g][e][d] : W_out[g][e-256][d]
__global__ void pack_weights_kernel(const float* __restrict__ Wa,
                                    const float* __restrict__ Wb,
                                    float* __restrict__ out)
{
    int idx = blockIdx.x * blockDim.x + threadIdx.x;   // 0 .. 512*1024-1
    if (idx >= K_TOT * N_TOT) return;
    int e = idx >> 10;          // 0..511
    int j = idx & 1023;         // g*256+d
    int g = j >> 8;
    int d = j & 255;
    float v = (e < DD) ? Wa[g * DD * DD + e * DD + d]
                       : Wb[g * DD * DD + (e - DD) * DD + d];
    out[idx] = v;
}

// ---------------- gather-aggregate -----------------------------------------
// Hin[m][:] = node_mask[m] * sum_k in_mask[m][k] * h[b, in_nodes[m][k], :]
// 4 nodes per 256-thread block; 64 threads (float4 lanes) per node.
__global__ __launch_bounds__(256) void gather_kernel(
    const float* __restrict__ h,
    const int*   __restrict__ in_nodes,  const float* __restrict__ in_mask,
    const int*   __restrict__ out_nodes, const float* __restrict__ out_mask,
    const float* __restrict__ node_mask,
    float* __restrict__ Hin, float* __restrict__ Hout)
{
    int m  = blockIdx.x * 4 + (threadIdx.x >> 6);     // node row 0..8191
    int d4 = (threadIdx.x & 63);                      // float4 lane 0..63
    float nm = node_mask[m];
    float4* pin  = reinterpret_cast<float4*>(Hin  + (size_t)m * DD) + d4;
    float4* pout = reinterpret_cast<float4*>(Hout + (size_t)m * DD) + d4;
    if (nm == 0.f) {
        float4 z = {0.f, 0.f, 0.f, 0.f};
        *pin = z; *pout = z;
        return;
    }
    const float* hb = h + (size_t)(m >> 10) * NN * DD;  // batch base
    int base = m * KK;
    float4 ai = {0.f,0.f,0.f,0.f};
    float4 ao = {0.f,0.f,0.f,0.f};
    #pragma unroll
    for (int k = 0; k < KK; k++) {
        int   ni = in_nodes[base + k];
        float wi = in_mask [base + k];
        float4 v = *(reinterpret_cast<const float4*>(hb + (size_t)ni * DD) + d4);
        ai.x += wi * v.x; ai.y += wi * v.y; ai.z += wi * v.z; ai.w += wi * v.w;
        int   no = out_nodes[base + k];
        float wo = out_mask [base + k];
        float4 u = *(reinterpret_cast<const float4*>(hb + (size_t)no * DD) + d4);
        ao.x += wo * u.x; ao.y += wo * u.y; ao.z += wo * u.z; ao.w += wo * u.w;
    }
    ai.x *= nm; ai.y *= nm; ai.z *= nm; ai.w *= nm;
    ao.x *= nm; ao.y *= nm; ao.z *= nm; ao.w *= nm;
    *pin = ai; *pout = ao;
}

// ---------------- SGEMM: C = [A0|A1] @ B + Cadd ----------------------------
// A0,A1: [8192,256] row-major halves; B: [512,1024]; Cout: [8192,1024].
// mode 0: Cadd is bias row [1024];  mode 1: Cadd is full [8192,1024].
// 128x128 block tile, BK=8, 256 threads, 8x8 per-thread (4+4 split).
#define BM 128
#define BN 128
#define BKD 8
__global__ __launch_bounds__(256) void gemm_kernel(
    const float* __restrict__ A0, const float* __restrict__ A1,
    const float* __restrict__ Bmat,
    const float* __restrict__ Cadd,
    float* __restrict__ Cout, int mode)
{
    __shared__ float As[BKD][BM];
    __shared__ float Bs[BKD][BN];

    const int tid = threadIdx.x;
    const int bm = blockIdx.y * BM;
    const int bn = blockIdx.x * BN;
    const int tx = tid & 15;          // col group
    const int ty = tid >> 4;          // row group

    // A loader: thread -> row ar (0..127), col group ac in {0,4}
    const int ar = tid >> 1;
    const int ac = (tid & 1) * 4;
    // B loader: row br (0..7), col bc (0..124 step 4)
    const int br = tid >> 5;
    const int bc = (tid & 31) * 4;

    float acc[8][8];
    #pragma unroll
    for (int i = 0; i < 8; i++)
        #pragma unroll
        for (int j = 0; j < 8; j++) acc[i][j] = 0.f;

    for (int k0 = 0; k0 < K_TOT; k0 += BKD) {
        // load A tile (pick half based on global k column)
        int gc = k0 + ac;
        const float* Asrc = (gc < DD)
            ? (A0 + (size_t)(bm + ar) * DD + gc)
            : (A1 + (size_t)(bm + ar) * DD + (gc - DD));
        float4 av = *reinterpret_cast<const float4*>(Asrc);
        As[ac + 0][ar] = av.x;
        As[ac + 1][ar] = av.y;
        As[ac + 2][ar] = av.z;
        As[ac + 3][ar] = av.w;
        // load B tile
        float4 bv = *reinterpret_cast<const float4*>(
            Bmat + (size_t)(k0 + br) * N_TOT + bn + bc);
        *reinterpret_cast<float4*>(&Bs[br][bc]) = bv;
        __syncthreads();

        #pragma unroll
        for (int kk = 0; kk < BKD; kk++) {
            float a[8], b[8];
            float4 a0 = *reinterpret_cast<const float4*>(&As[kk][ty * 4]);
            float4 a1 = *reinterpret_cast<const float4*>(&As[kk][64 + ty * 4]);
            a[0]=a0.x; a[1]=a0.y; a[2]=a0.z; a[3]=a0.w;
            a[4]=a1.x; a[5]=a1.y; a[6]=a1.z; a[7]=a1.w;
            float4 b0 = *reinterpret_cast<const float4*>(&Bs[kk][tx * 4]);
            float4 b1 = *reinterpret_cast<const float4*>(&Bs[kk][64 + tx * 4]);
            b[0]=b0.x; b[1]=b0.y; b[2]=b0.z; b[3]=b0.w;
            b[4]=b1.x; b[5]=b1.y; b[6]=b1.z; b[7]=b1.w;
            #pragma unroll
            for (int i = 0; i < 8; i++)
                #pragma unroll
                for (int j = 0; j < 8; j++)
                    acc[i][j] += a[i] * b[j];
        }
        __syncthreads();
    }

    // epilogue: rows (i<4 ? ty*4+i : 64+ty*4+i-4), cols same split on tx
    #pragma unroll
    for (int i = 0; i < 8; i++) {
        int gm = bm + ty * 4 + (i & 3) + ((i >> 2) * 64);
        #pragma unroll
        for (int jh = 0; jh < 2; jh++) {
            int gn = bn + tx * 4 + jh * 64;
            float4 cv;
            if (mode == 0) {
                cv = *reinterpret_cast<const float4*>(Cadd + gn);
            } else {
                cv = *reinterpret_cast<const float4*>(Cadd + (size_t)gm * N_TOT + gn);
            }
            float4 ov;
            ov.x = acc[i][jh * 4 + 0] + cv.x;
            ov.y = acc[i][jh * 4 + 1] + cv.y;
            ov.z = acc[i][jh * 4 + 2] + cv.z;
            ov.w = acc[i][jh * 4 + 3] + cv.w;
            *reinterpret_cast<float4*>(Cout + (size_t)gm * N_TOT + gn) = ov;
        }
    }
}

// ---------------- LSTM pointwise -------------------------------------------
__device__ __forceinline__ float sigf(float x) {
    return 1.f / (1.f + __expf(-x));
}

__global__ __launch_bounds__(256) void lstm_pointwise_kernel(
    const float* __restrict__ pre,
    const float* __restrict__ c_in,
    const float* __restrict__ node_mask,
    float* __restrict__ c_out,
    float* __restrict__ h_out)
{
    int idx = blockIdx.x * blockDim.x + threadIdx.x;
    if (idx >= M_TOT * DD) return;
    int m = idx >> 8;
    int d = idx & 255;
    const float* p = pre + (size_t)m * N_TOT + d;
    float i_g = sigf(p[0]);
    float o_g = sigf(p[DD]);
    float f_g = sigf(p[2 * DD]);
    float g   = tanhf(p[3 * DD]);
    float nm  = node_mask[m];
    float c   = (f_g * c_in[idx] + i_g * g) * nm;
    c_out[idx] = c;
    h_out[idx] = o_g * tanhf(c) * nm;
}

// ---------------- launch ----------------------------------------------------
extern "C" void kernel_launch(void* const* d_in, const int* in_sizes, int n_in,
                              void* d_out, int out_size)
{
    const float* h0        = (const float*)d_in[0];
    const float* c0        = (const float*)d_in[1];
    const float* x_in      = (const float*)d_in[2];
    const float* x_out     = (const float*)d_in[3];
    const float* W_in      = (const float*)d_in[4];
    const float* U_in      = (const float*)d_in[5];
    const float* W_out     = (const float*)d_in[6];
    const float* U_out     = (const float*)d_in[7];
    const float* bias      = (const float*)d_in[8];
    const float* in_mask   = (const float*)d_in[9];
    const float* out_mask  = (const float*)d_in[10];
    const float* node_mask = (const float*)d_in[11];
    const int*   in_nodes  = (const int*)d_in[12];
    const int*   out_nodes = (const int*)d_in[13];
    // d_in[14] = num_layers (fixed = 3 for this problem)

    float *Wpack, *Upack, *xw, *pre, *Hin, *Hout, *hbuf, *cbuf;
    cudaGetSymbolAddress((void**)&Wpack, g_Wpack);
    cudaGetSymbolAddress((void**)&Upack, g_Upack);
    cudaGetSymbolAddress((void**)&xw,    g_xw);
    cudaGetSymbolAddress((void**)&pre,   g_pre);
    cudaGetSymbolAddress((void**)&Hin,   g_Hin);
    cudaGetSymbolAddress((void**)&Hout,  g_Hout);
    cudaGetSymbolAddress((void**)&hbuf,  g_h);
    cudaGetSymbolAddress((void**)&cbuf,  g_c);

    float* out = (float*)d_out;

    const int packElems = K_TOT * N_TOT;
    pack_weights_kernel<<<(packElems + 255) / 256, 256>>>(W_in,  W_out, Wpack);
    pack_weights_kernel<<<(packElems + 255) / 256, 256>>>(U_in,  U_out, Upack);

    dim3 ggrid(N_TOT / BN, M_TOT / BM);   // (8, 64)

    // layer-invariant x contribution + bias
    gemm_kernel<<<ggrid, 256>>>(x_in, x_out, Wpack, bias, xw, 0);

    const int pwBlocks = (M_TOT * DD + 255) / 256;

    for (int layer = 0; layer < LL; layer++) {
        const float* hsrc = (layer == 0) ? h0 : hbuf;
        const float* csrc = (layer == 0) ? c0 : cbuf;
        float* hdst = (layer == LL - 1) ? out : hbuf;

        gather_kernel<<<M_TOT / 4, 256>>>(hsrc, in_nodes, in_mask,
                                          out_nodes, out_mask, node_mask,
                                          Hin, Hout);
        gemm_kernel<<<ggrid, 256>>>(Hin, Hout, Upack, xw, pre, 1);
        lstm_pointwise_kernel<<<pwBlocks, 256>>>(pre, csrc, node_mask,
                                                 cbuf, hdst);
    }
}

// round 4
// speedup vs baseline: 1.5932x; 1.5932x over previous
#include <cuda_runtime.h>
#include <cuda_bf16.h>
#include <cstdint>

// Fixed problem shape: B=8, N=1024, K=16, D=256, L=3
#define M_TOT   8192
#define DDIM    256
#define KNBR    16
#define LLAYERS 3
#define K_HALF  512          // packed activation width ([in|out] halves)
#define N_TOT   1024         // 4 gates x 256, interleaved as j = 4*d+g
#define NCHUNKS 48           // 3 segments (hh, hl, lh) x 16 chunks of k=32

// ---------------- device scratch (static; no runtime alloc) ----------------
__device__ __align__(256) __nv_bfloat16 g_Bw_hi[N_TOT * K_HALF];
__device__ __align__(256) __nv_bfloat16 g_Bw_lo[N_TOT * K_HALF];
__device__ __align__(256) __nv_bfloat16 g_Bu_hi[N_TOT * K_HALF];
__device__ __align__(256) __nv_bfloat16 g_Bu_lo[N_TOT * K_HALF];
__device__ __align__(256) __nv_bfloat16 g_Ax_hi[M_TOT * K_HALF];
__device__ __align__(256) __nv_bfloat16 g_Ax_lo[M_TOT * K_HALF];
__device__ __align__(256) __nv_bfloat16 g_Ah_hi[M_TOT * K_HALF];
__device__ __align__(256) __nv_bfloat16 g_Ah_lo[M_TOT * K_HALF];
__device__ __align__(256) float g_xw[M_TOT * N_TOT];     // interleaved cols
__device__ __align__(256) float g_h[M_TOT * DDIM];
__device__ __align__(256) float g_c[M_TOT * DDIM];
__device__ __align__(256) float g_bias[N_TOT];

// ---------------- PTX helpers ----------------------------------------------
__device__ __forceinline__ uint32_t smem_u32(const void* p) {
    uint32_t a;
    asm("{ .reg .u64 t; cvta.to.shared.u64 t, %1; cvt.u32.u64 %0, t; }"
        : "=r"(a) : "l"(p));
    return a;
}
__device__ __forceinline__ void cp_async16(uint32_t dst, const void* src) {
    asm volatile("cp.async.cg.shared.global [%0], [%1], 16;\n"
                 :: "r"(dst), "l"(src));
}
#define CP_COMMIT() asm volatile("cp.async.commit_group;" ::: "memory")
#define CP_WAIT2()  asm volatile("cp.async.wait_group 2;" ::: "memory")

#define LDSM_X4(r0, r1, r2, r3, addr) \
    asm volatile("ldmatrix.sync.aligned.m8n8.x4.shared.b16 {%0,%1,%2,%3}, [%4];" \
        : "=r"(r0), "=r"(r1), "=r"(r2), "=r"(r3) : "r"(addr))

#define MMA16816(d, a, b) \
    asm volatile("mma.sync.aligned.m16n8k16.row.col.f32.bf16.bf16.f32 " \
        "{%0,%1,%2,%3}, {%4,%5,%6,%7}, {%8,%9}, {%0,%1,%2,%3};" \
        : "+f"((d)[0]), "+f"((d)[1]), "+f"((d)[2]), "+f"((d)[3]) \
        : "r"((a)[0]), "r"((a)[1]), "r"((a)[2]), "r"((a)[3]), \
          "r"((b)[0]), "r"((b)[1]))

// ---------------- hi/lo split helpers ---------------------------------------
__device__ __forceinline__ void split_store4(__nv_bfloat16* hp, __nv_bfloat16* lp,
                                             float4 v) {
    __nv_bfloat16 h0 = __float2bfloat16_rn(v.x);
    __nv_bfloat16 h1 = __float2bfloat16_rn(v.y);
    __nv_bfloat16 h2 = __float2bfloat16_rn(v.z);
    __nv_bfloat16 h3 = __float2bfloat16_rn(v.w);
    __nv_bfloat16 l0 = __float2bfloat16_rn(v.x - __bfloat162float(h0));
    __nv_bfloat16 l1 = __float2bfloat16_rn(v.y - __bfloat162float(h1));
    __nv_bfloat16 l2 = __float2bfloat16_rn(v.z - __bfloat162float(h2));
    __nv_bfloat16 l3 = __float2bfloat16_rn(v.w - __bfloat162float(h3));
    __nv_bfloat162* hp2 = reinterpret_cast<__nv_bfloat162*>(hp);
    __nv_bfloat162* lp2 = reinterpret_cast<__nv_bfloat162*>(lp);
    hp2[0] = __nv_bfloat162(h0, h1); hp2[1] = __nv_bfloat162(h2, h3);
    lp2[0] = __nv_bfloat162(l0, l1); lp2[1] = __nv_bfloat162(l2, l3);
}

// ---------------- weight pack: Bt[j][e], j = 4*d+g, hi/lo -------------------
__global__ void pack_w_kernel(const float* __restrict__ Wa,
                              const float* __restrict__ Wb,
                              __nv_bfloat16* __restrict__ Bhi,
                              __nv_bfloat16* __restrict__ Blo)
{
    int idx = blockIdx.x * blockDim.x + threadIdx.x;   // 1024*512
    if (idx >= N_TOT * K_HALF) return;
    int j = idx >> 9;          // 0..1023 interleaved col
    int e = idx & 511;         // 0..511
    int d = j >> 2;
    int g = j & 3;
    float v = (e < DDIM) ? Wa[g * DDIM * DDIM + e * DDIM + d]
                         : Wb[g * DDIM * DDIM + (e - DDIM) * DDIM + d];
    __nv_bfloat16 h = __float2bfloat16_rn(v);
    Bhi[idx] = h;
    Blo[idx] = __float2bfloat16_rn(v - __bfloat162float(h));
}

__global__ void pack_bias_kernel(const float* __restrict__ b, float* __restrict__ bi)
{
    int j = blockIdx.x * blockDim.x + threadIdx.x;
    if (j >= N_TOT) return;
    bi[j] = b[(j & 3) * DDIM + (j >> 2)];
}

// ---------------- x conversion: Ax[m][0:256]=x_in, [256:512]=x_out ----------
__global__ __launch_bounds__(256) void convert_x_kernel(
    const float* __restrict__ x_in, const float* __restrict__ x_out,
    __nv_bfloat16* __restrict__ Ahi, __nv_bfloat16* __restrict__ Alo)
{
    int idx4 = blockIdx.x * blockDim.x + threadIdx.x;   // 8192*128
    if (idx4 >= M_TOT * 128) return;
    int m = idx4 >> 7;
    int c4 = idx4 & 127;
    float4 v = (c4 < 64)
        ? *reinterpret_cast<const float4*>(x_in + (size_t)m * DDIM + c4 * 4)
        : *reinterpret_cast<const float4*>(x_out + (size_t)m * DDIM + (c4 - 64) * 4);
    split_store4(Ahi + (size_t)m * K_HALF + c4 * 4,
                 Alo + (size_t)m * K_HALF + c4 * 4, v);
}

// ---------------- gather-aggregate -> bf16 hi/lo packed activations --------
__global__ __launch_bounds__(256) void gather_kernel(
    const float* __restrict__ h,
    const int*   __restrict__ in_nodes,  const float* __restrict__ in_mask,
    const int*   __restrict__ out_nodes, const float* __restrict__ out_mask,
    const float* __restrict__ node_mask,
    __nv_bfloat16* __restrict__ Ahi, __nv_bfloat16* __restrict__ Alo)
{
    int m  = blockIdx.x * 4 + (threadIdx.x >> 6);
    int d4 = threadIdx.x & 63;
    float nm = node_mask[m];
    __nv_bfloat16* hin  = Ahi + (size_t)m * K_HALF + 4 * d4;
    __nv_bfloat16* lin  = Alo + (size_t)m * K_HALF + 4 * d4;
    __nv_bfloat16* hout = hin + DDIM;
    __nv_bfloat16* lout = lin + DDIM;
    float4 ai = {0.f, 0.f, 0.f, 0.f};
    float4 ao = {0.f, 0.f, 0.f, 0.f};
    if (nm != 0.f) {
        const float* hb = h + (size_t)(m >> 10) * 1024 * DDIM;
        int base = m * KNBR;
        #pragma unroll
        for (int k = 0; k < KNBR; k++) {
            int   ni = in_nodes[base + k];
            float wi = in_mask [base + k];
            float4 v = *(reinterpret_cast<const float4*>(hb + (size_t)ni * DDIM) + d4);
            ai.x += wi * v.x; ai.y += wi * v.y; ai.z += wi * v.z; ai.w += wi * v.w;
            int   no = out_nodes[base + k];
            float wo = out_mask [base + k];
            float4 u = *(reinterpret_cast<const float4*>(hb + (size_t)no * DDIM) + d4);
            ao.x += wo * u.x; ao.y += wo * u.y; ao.z += wo * u.z; ao.w += wo * u.w;
        }
        ai.x *= nm; ai.y *= nm; ai.z *= nm; ai.w *= nm;
        ao.x *= nm; ao.y *= nm; ao.z *= nm; ao.w *= nm;
    }
    split_store4(hin, lin, ai);
    split_store4(hout, lout, ao);
}

// ---------------- HMMA GEMM + fused epilogue -------------------------------
// CTA tile 128x128, warp tile 64x32, mma.sync m16n8k16 bf16.
// K' = 1536 total (3 segments x 512), chunks of 32, 3-stage cp.async pipe.
// SMEM per stage: A 128x(64+16pad) + B 128x(64+16pad) = 20480 B; 3 stages.
#define PADROW  80
#define ABUF_SZ (128 * PADROW)
#define STAGE_SZ (2 * ABUF_SZ)
#define SMEM_REQ (3 * STAGE_SZ)

__device__ __forceinline__ float sigf(float x) { return 1.f / (1.f + __expf(-x)); }

__device__ __forceinline__ void load_chunk(
    uint32_t smA, uint32_t smB,
    const __nv_bfloat16* Aseg, const __nv_bfloat16* Bseg,
    int m0, int n0, int kc, int tid)
{
    const char* Ab = reinterpret_cast<const char*>(Aseg) +
                     ((size_t)m0 * K_HALF + kc) * 2;
    const char* Bb = reinterpret_cast<const char*>(Bseg) +
                     ((size_t)n0 * K_HALF + kc) * 2;
    #pragma unroll
    for (int i = 0; i < 2; i++) {
        int idx = tid + i * 256;           // 0..511
        int r = idx >> 2;                  // 0..127
        int c = idx & 3;                   // 0..3 (16B cols)
        cp_async16(smA + r * PADROW + c * 16, Ab + (size_t)r * (K_HALF * 2) + c * 16);
        cp_async16(smB + r * PADROW + c * 16, Bb + (size_t)r * (K_HALF * 2) + c * 16);
    }
    CP_COMMIT();
}

__global__ __launch_bounds__(256, 2) void gemm_fused_kernel(
    const __nv_bfloat16* __restrict__ Ahi, const __nv_bfloat16* __restrict__ Alo,
    const __nv_bfloat16* __restrict__ Bhi, const __nv_bfloat16* __restrict__ Blo,
    const float* __restrict__ addend,      // bias (mode0) or xw (mode1)
    const float* __restrict__ c_in, const float* __restrict__ node_mask,
    float* __restrict__ c_out, float* __restrict__ h_out,
    float* __restrict__ xw_out, int mode)
{
    extern __shared__ __align__(128) char smem_raw[];
    const uint32_t sb = smem_u32(smem_raw);
    const int tid  = threadIdx.x;
    const int wid  = tid >> 5;
    const int lane = tid & 31;
    const int m0 = blockIdx.y * 128;
    const int n0 = blockIdx.x * 128;
    const int wm = (wid >> 2) * 64;       // warp M offset (2 rows of warps)
    const int wn = (wid & 3) * 32;        // warp N offset (4 cols of warps)

    float acc[4][4][4];
    #pragma unroll
    for (int a = 0; a < 4; a++)
        #pragma unroll
        for (int b = 0; b < 4; b++)
            #pragma unroll
            for (int q = 0; q < 4; q++) acc[a][b][q] = 0.f;

    const __nv_bfloat16* Asegs[3] = {Ahi, Ahi, Alo};
    const __nv_bfloat16* Bsegs[3] = {Bhi, Blo, Bhi};

    // prologue: fill 3 stages
    #pragma unroll
    for (int s = 0; s < 3; s++) {
        int seg = s >> 4;                  // 0 for s<16 (always 0 here)
        int kc  = (s & 15) * 32;
        uint32_t smA = sb + s * STAGE_SZ;
        load_chunk(smA, smA + ABUF_SZ, Asegs[seg], Bsegs[seg], m0, n0, kc, tid);
    }

    const int ldrow = lane & 15;
    const int ldcol = (lane >> 4) << 4;

    for (int c = 0; c < NCHUNKS; c++) {
        CP_WAIT2();
        __syncthreads();
        uint32_t smA = sb + (c % 3) * STAGE_SZ;
        uint32_t smB = smA + ABUF_SZ;

        #pragma unroll
        for (int ks = 0; ks < 2; ks++) {
            uint32_t aF[4][4];
            uint32_t bF[4][2];
            #pragma unroll
            for (int mi = 0; mi < 4; mi++) {
                uint32_t addr = smA + (wm + mi * 16 + ldrow) * PADROW +
                                ks * 32 + ldcol;
                LDSM_X4(aF[mi][0], aF[mi][1], aF[mi][2], aF[mi][3], addr);
            }
            #pragma unroll
            for (int nj = 0; nj < 2; nj++) {
                uint32_t r0, r1, r2, r3;
                uint32_t addr = smB + (wn + nj * 16 + ldrow) * PADROW +
                                ks * 32 + ldcol;
                LDSM_X4(r0, r1, r2, r3, addr);
                bF[nj * 2 + 0][0] = r0; bF[nj * 2 + 0][1] = r2;
                bF[nj * 2 + 1][0] = r1; bF[nj * 2 + 1][1] = r3;
            }
            #pragma unroll
            for (int mi = 0; mi < 4; mi++)
                #pragma unroll
                for (int nb = 0; nb < 4; nb++)
                    MMA16816(acc[mi][nb], aF[mi], bF[nb]);
        }
        __syncthreads();
        if (c + 3 < NCHUNKS) {
            int kt  = c + 3;
            int seg = kt >> 4;
            int kc  = (kt & 15) * 32;
            uint32_t dA = sb + (kt % 3) * STAGE_SZ;
            load_chunk(dA, dA + ABUF_SZ, Asegs[seg], Bsegs[seg], m0, n0, kc, tid);
        }
    }

    // ---- epilogue -------------------------------------------------------
    if (mode == 0) {
        #pragma unroll
        for (int mi = 0; mi < 4; mi++) {
            int mlo = m0 + wm + mi * 16 + (lane >> 2);
            #pragma unroll
            for (int nb = 0; nb < 4; nb++) {
                int j = n0 + wn + nb * 8 + (lane & 3) * 2;
                float2 b2 = *reinterpret_cast<const float2*>(addend + j);
                float2 v0 = {acc[mi][nb][0] + b2.x, acc[mi][nb][1] + b2.y};
                float2 v1 = {acc[mi][nb][2] + b2.x, acc[mi][nb][3] + b2.y};
                *reinterpret_cast<float2*>(xw_out + (size_t)mlo * N_TOT + j) = v0;
                *reinterpret_cast<float2*>(xw_out + (size_t)(mlo + 8) * N_TOT + j) = v1;
            }
        }
    } else {
        const int p = lane & 1;
        #pragma unroll
        for (int mi = 0; mi < 4; mi++) {
            int m = m0 + wm + mi * 16 + (lane >> 2) + p * 8;
            float nm = node_mask[m];
            #pragma unroll
            for (int nb = 0; nb < 4; nb++) {
                float* a = acc[mi][nb];
                float o0 = __shfl_xor_sync(0xffffffffu, a[0], 1);
                float o1 = __shfl_xor_sync(0xffffffffu, a[1], 1);
                float o2 = __shfl_xor_sync(0xffffffffu, a[2], 1);
                float o3 = __shfl_xor_sync(0xffffffffu, a[3], 1);
                int dg = ((n0 + wn + nb * 8) >> 2) + ((lane & 3) >> 1);
                float vi, vo, vf, vg;
                if (p == 0) { vi = a[0]; vo = a[1]; vf = o0; vg = o1; }
                else        { vi = o2;  vo = o3;  vf = a[2]; vg = a[3]; }
                float4 xv = *reinterpret_cast<const float4*>(
                    addend + (size_t)m * N_TOT + dg * 4);
                float ig = sigf(vi + xv.x);
                float og = sigf(vo + xv.y);
                float fg = sigf(vf + xv.z);
                float gg = tanhf(vg + xv.w);
                float cv = c_in[(size_t)m * DDIM + dg];
                float cn = (fg * cv + ig * gg) * nm;
                c_out[(size_t)m * DDIM + dg] = cn;
                h_out[(size_t)m * DDIM + dg] = og * tanhf(cn) * nm;
            }
        }
    }
}

// ---------------- launch ----------------------------------------------------
extern "C" void kernel_launch(void* const* d_in, const int* in_sizes, int n_in,
                              void* d_out, int out_size)
{
    const float* h0        = (const float*)d_in[0];
    const float* c0        = (const float*)d_in[1];
    const float* x_in      = (const float*)d_in[2];
    const float* x_out     = (const float*)d_in[3];
    const float* W_in      = (const float*)d_in[4];
    const float* U_in      = (const float*)d_in[5];
    const float* W_out     = (const float*)d_in[6];
    const float* U_out     = (const float*)d_in[7];
    const float* bias      = (const float*)d_in[8];
    const float* in_mask   = (const float*)d_in[9];
    const float* out_mask  = (const float*)d_in[10];
    const float* node_mask = (const float*)d_in[11];
    const int*   in_nodes  = (const int*)d_in[12];
    const int*   out_nodes = (const int*)d_in[13];

    __nv_bfloat16 *Bwh, *Bwl, *Buh, *Bul, *Axh, *Axl, *Ahh, *Ahl;
    float *xw, *hbuf, *cbuf, *bi;
    cudaGetSymbolAddress((void**)&Bwh, g_Bw_hi);
    cudaGetSymbolAddress((void**)&Bwl, g_Bw_lo);
    cudaGetSymbolAddress((void**)&Buh, g_Bu_hi);
    cudaGetSymbolAddress((void**)&Bul, g_Bu_lo);
    cudaGetSymbolAddress((void**)&Axh, g_Ax_hi);
    cudaGetSymbolAddress((void**)&Axl, g_Ax_lo);
    cudaGetSymbolAddress((void**)&Ahh, g_Ah_hi);
    cudaGetSymbolAddress((void**)&Ahl, g_Ah_lo);
    cudaGetSymbolAddress((void**)&xw,   g_xw);
    cudaGetSymbolAddress((void**)&hbuf, g_h);
    cudaGetSymbolAddress((void**)&cbuf, g_c);
    cudaGetSymbolAddress((void**)&bi,   g_bias);

    float* out = (float*)d_out;

    cudaFuncSetAttribute(gemm_fused_kernel,
                         cudaFuncAttributeMaxDynamicSharedMemorySize, SMEM_REQ);

    pack_w_kernel<<<(N_TOT * K_HALF + 255) / 256, 256>>>(W_in, W_out, Bwh, Bwl);
    pack_w_kernel<<<(N_TOT * K_HALF + 255) / 256, 256>>>(U_in, U_out, Buh, Bul);
    pack_bias_kernel<<<4, 256>>>(bias, bi);
    convert_x_kernel<<<(M_TOT * 128 + 255) / 256, 256>>>(x_in, x_out, Axh, Axl);

    dim3 ggrid(N_TOT / 128, M_TOT / 128);   // (8, 64)

    // layer-invariant xw = x @ W + bias  (interleaved columns)
    gemm_fused_kernel<<<ggrid, 256, SMEM_REQ>>>(
        Axh, Axl, Bwh, Bwl, bi, nullptr, nullptr, nullptr, nullptr, xw, 0);

    for (int layer = 0; layer < LLAYERS; layer++) {
        const float* hsrc = (layer == 0) ? h0 : hbuf;
        const float* csrc = (layer == 0) ? c0 : cbuf;
        float* hdst = (layer == LLAYERS - 1) ? out : hbuf;

        gather_kernel<<<M_TOT / 4, 256>>>(hsrc, in_nodes, in_mask,
                                          out_nodes, out_mask, node_mask,
                                          Ahh, Ahl);
        gemm_fused_kernel<<<ggrid, 256, SMEM_REQ>>>(
            Ahh, Ahl, Buh, Bul, xw, csrc, node_mask, cbuf, hdst, nullptr, 1);
    }
}

// round 5
// speedup vs baseline: 1.9667x; 1.2344x over previous
#include <cuda_runtime.h>
#include <cuda_bf16.h>
#include <cstdint>

// Fixed problem shape: B=8, N=1024, K=16, D=256, L=3
#define M_TOT   8192
#define DDIM    256
#define KNBR    16
#define LLAYERS 3
#define K_HALF  512          // packed activation width ([in|out] halves)
#define N_TOT   1024         // 4 gates x 256, interleaved as j = 4*d+g
#define NCHUNKS 24           // 3 segments (hh, hl, lh) x 8 chunks of k=64

// ---------------- device scratch (static; no runtime alloc) ----------------
__device__ __align__(256) __nv_bfloat16 g_Bw_hi[N_TOT * K_HALF];
__device__ __align__(256) __nv_bfloat16 g_Bw_lo[N_TOT * K_HALF];
__device__ __align__(256) __nv_bfloat16 g_Bu_hi[N_TOT * K_HALF];
__device__ __align__(256) __nv_bfloat16 g_Bu_lo[N_TOT * K_HALF];
__device__ __align__(256) __nv_bfloat16 g_Ax_hi[M_TOT * K_HALF];
__device__ __align__(256) __nv_bfloat16 g_Ax_lo[M_TOT * K_HALF];
__device__ __align__(256) __nv_bfloat16 g_Ah_hi[M_TOT * K_HALF];
__device__ __align__(256) __nv_bfloat16 g_Ah_lo[M_TOT * K_HALF];
__device__ __align__(256) float g_xw[M_TOT * N_TOT];     // interleaved cols
__device__ __align__(256) float g_h[M_TOT * DDIM];
__device__ __align__(256) float g_c[M_TOT * DDIM];
__device__ __align__(256) float g_bias[N_TOT];

// ---------------- PTX helpers ----------------------------------------------
__device__ __forceinline__ uint32_t smem_u32(const void* p) {
    uint32_t a;
    asm("{ .reg .u64 t; cvta.to.shared.u64 t, %1; cvt.u32.u64 %0, t; }"
        : "=r"(a) : "l"(p));
    return a;
}
__device__ __forceinline__ void cp_async16(uint32_t dst, const void* src) {
    asm volatile("cp.async.cg.shared.global [%0], [%1], 16;\n"
                 :: "r"(dst), "l"(src));
}
#define CP_COMMIT() asm volatile("cp.async.commit_group;" ::: "memory")
#define CP_WAIT1()  asm volatile("cp.async.wait_group 1;" ::: "memory")
#define CP_WAIT0()  asm volatile("cp.async.wait_group 0;" ::: "memory")

#define LDSM_X4(r0, r1, r2, r3, addr) \
    asm volatile("ldmatrix.sync.aligned.m8n8.x4.shared.b16 {%0,%1,%2,%3}, [%4];" \
        : "=r"(r0), "=r"(r1), "=r"(r2), "=r"(r3) : "r"(addr))

#define MMA16816(d, a, b) \
    asm volatile("mma.sync.aligned.m16n8k16.row.col.f32.bf16.bf16.f32 " \
        "{%0,%1,%2,%3}, {%4,%5,%6,%7}, {%8,%9}, {%0,%1,%2,%3};" \
        : "+f"((d)[0]), "+f"((d)[1]), "+f"((d)[2]), "+f"((d)[3]) \
        : "r"((a)[0]), "r"((a)[1]), "r"((a)[2]), "r"((a)[3]), \
          "r"((b)[0]), "r"((b)[1]))

// ---------------- hi/lo split helpers ---------------------------------------
__device__ __forceinline__ void split_store4(__nv_bfloat16* hp, __nv_bfloat16* lp,
                                             float4 v) {
    __nv_bfloat16 h0 = __float2bfloat16_rn(v.x);
    __nv_bfloat16 h1 = __float2bfloat16_rn(v.y);
    __nv_bfloat16 h2 = __float2bfloat16_rn(v.z);
    __nv_bfloat16 h3 = __float2bfloat16_rn(v.w);
    __nv_bfloat16 l0 = __float2bfloat16_rn(v.x - __bfloat162float(h0));
    __nv_bfloat16 l1 = __float2bfloat16_rn(v.y - __bfloat162float(h1));
    __nv_bfloat16 l2 = __float2bfloat16_rn(v.z - __bfloat162float(h2));
    __nv_bfloat16 l3 = __float2bfloat16_rn(v.w - __bfloat162float(h3));
    __nv_bfloat162* hp2 = reinterpret_cast<__nv_bfloat162*>(hp);
    __nv_bfloat162* lp2 = reinterpret_cast<__nv_bfloat162*>(lp);
    hp2[0] = __nv_bfloat162(h0, h1); hp2[1] = __nv_bfloat162(h2, h3);
    lp2[0] = __nv_bfloat162(l0, l1); lp2[1] = __nv_bfloat162(l2, l3);
}

// ---------------- weight pack: Bt[j][e], j = 4*d+g, hi/lo -------------------
__global__ void pack_w_kernel(const float* __restrict__ Wa,
                              const float* __restrict__ Wb,
                              __nv_bfloat16* __restrict__ Bhi,
                              __nv_bfloat16* __restrict__ Blo)
{
    int idx = blockIdx.x * blockDim.x + threadIdx.x;   // 1024*512
    if (idx >= N_TOT * K_HALF) return;
    int j = idx >> 9;          // 0..1023 interleaved col
    int e = idx & 511;         // 0..511
    int d = j >> 2;
    int g = j & 3;
    float v = (e < DDIM) ? Wa[g * DDIM * DDIM + e * DDIM + d]
                         : Wb[g * DDIM * DDIM + (e - DDIM) * DDIM + d];
    __nv_bfloat16 h = __float2bfloat16_rn(v);
    Bhi[idx] = h;
    Blo[idx] = __float2bfloat16_rn(v - __bfloat162float(h));
}

__global__ void pack_bias_kernel(const float* __restrict__ b, float* __restrict__ bi)
{
    int j = blockIdx.x * blockDim.x + threadIdx.x;
    if (j >= N_TOT) return;
    bi[j] = b[(j & 3) * DDIM + (j >> 2)];
}

// ---------------- x conversion: Ax[m][0:256]=x_in, [256:512]=x_out ----------
__global__ __launch_bounds__(256) void convert_x_kernel(
    const float* __restrict__ x_in, const float* __restrict__ x_out,
    __nv_bfloat16* __restrict__ Ahi, __nv_bfloat16* __restrict__ Alo)
{
    int idx4 = blockIdx.x * blockDim.x + threadIdx.x;   // 8192*128
    if (idx4 >= M_TOT * 128) return;
    int m = idx4 >> 7;
    int c4 = idx4 & 127;
    float4 v = (c4 < 64)
        ? *reinterpret_cast<const float4*>(x_in + (size_t)m * DDIM + c4 * 4)
        : *reinterpret_cast<const float4*>(x_out + (size_t)m * DDIM + (c4 - 64) * 4);
    split_store4(Ahi + (size_t)m * K_HALF + c4 * 4,
                 Alo + (size_t)m * K_HALF + c4 * 4, v);
}

// ---------------- gather-aggregate -> bf16 hi/lo packed activations --------
__global__ __launch_bounds__(256) void gather_kernel(
    const float* __restrict__ h,
    const int*   __restrict__ in_nodes,  const float* __restrict__ in_mask,
    const int*   __restrict__ out_nodes, const float* __restrict__ out_mask,
    const float* __restrict__ node_mask,
    __nv_bfloat16* __restrict__ Ahi, __nv_bfloat16* __restrict__ Alo)
{
    int m  = blockIdx.x * 4 + (threadIdx.x >> 6);
    int d4 = threadIdx.x & 63;
    float nm = node_mask[m];
    __nv_bfloat16* hin  = Ahi + (size_t)m * K_HALF + 4 * d4;
    __nv_bfloat16* lin  = Alo + (size_t)m * K_HALF + 4 * d4;
    __nv_bfloat16* hout = hin + DDIM;
    __nv_bfloat16* lout = lin + DDIM;
    float4 ai = {0.f, 0.f, 0.f, 0.f};
    float4 ao = {0.f, 0.f, 0.f, 0.f};
    if (nm != 0.f) {
        const float* hb = h + (size_t)(m >> 10) * 1024 * DDIM;
        int base = m * KNBR;
        #pragma unroll
        for (int k = 0; k < KNBR; k++) {
            int   ni = in_nodes[base + k];
            float wi = in_mask [base + k];
            float4 v = *(reinterpret_cast<const float4*>(hb + (size_t)ni * DDIM) + d4);
            ai.x += wi * v.x; ai.y += wi * v.y; ai.z += wi * v.z; ai.w += wi * v.w;
            int   no = out_nodes[base + k];
            float wo = out_mask [base + k];
            float4 u = *(reinterpret_cast<const float4*>(hb + (size_t)no * DDIM) + d4);
            ao.x += wo * u.x; ao.y += wo * u.y; ao.z += wo * u.z; ao.w += wo * u.w;
        }
        ai.x *= nm; ai.y *= nm; ai.z *= nm; ai.w *= nm;
        ao.x *= nm; ao.y *= nm; ao.z *= nm; ao.w *= nm;
    }
    split_store4(hin, lin, ai);
    split_store4(hout, lout, ao);
}

// ---------------- HMMA GEMM + fused epilogue -------------------------------
// CTA tile 128x128, warp tile 64x32, mma.sync m16n8k16 bf16.
// K' = 1536 (3 segments x 512), chunks of 64, 3-stage cp.async pipeline,
// ONE __syncthreads per chunk, XOR-swizzled 128B rows (no padding).
#define ABUF_SZ  (128 * 128)          // 16 KB (128 rows x 128B)
#define STAGE_SZ (2 * ABUF_SZ)        // 32 KB
#define SMEM_REQ (3 * STAGE_SZ)       // 96 KB

__device__ __forceinline__ float sigf(float x) { return 1.f / (1.f + __expf(-x)); }

// swizzled smem byte offset for (row r, 16B-granule g)
__device__ __forceinline__ uint32_t sw_off(int r, int g) {
    return (uint32_t)(r * 128 + ((g ^ (r & 7)) << 4));
}

__device__ __forceinline__ void load_chunk(
    uint32_t smA, uint32_t smB,
    const __nv_bfloat16* Aseg, const __nv_bfloat16* Bseg,
    int m0, int n0, int kc, int tid)
{
    const char* Ab = reinterpret_cast<const char*>(Aseg) +
                     ((size_t)m0 * K_HALF + kc) * 2;
    const char* Bb = reinterpret_cast<const char*>(Bseg) +
                     ((size_t)n0 * K_HALF + kc) * 2;
    #pragma unroll
    for (int i = 0; i < 4; i++) {
        int idx = tid + i * 256;           // 0..1023
        int r = idx >> 3;                  // 0..127
        int g = idx & 7;                   // 16B granule
        size_t go = (size_t)r * (K_HALF * 2) + g * 16;
        cp_async16(smA + sw_off(r, g), Ab + go);
        cp_async16(smB + sw_off(r, g), Bb + go);
    }
    CP_COMMIT();
}

__global__ __launch_bounds__(256, 2) void gemm_fused_kernel(
    const __nv_bfloat16* __restrict__ Ahi, const __nv_bfloat16* __restrict__ Alo,
    const __nv_bfloat16* __restrict__ Bhi, const __nv_bfloat16* __restrict__ Blo,
    const float* __restrict__ addend,      // bias (mode0) or xw (mode1)
    const float* __restrict__ c_in, const float* __restrict__ node_mask,
    float* __restrict__ c_out, float* __restrict__ h_out,
    float* __restrict__ xw_out, int mode)
{
    extern __shared__ __align__(128) char smem_raw[];
    const uint32_t sb = smem_u32(smem_raw);
    const int tid  = threadIdx.x;
    const int wid  = tid >> 5;
    const int lane = tid & 31;
    const int m0 = blockIdx.y * 128;
    const int n0 = blockIdx.x * 128;
    const int wm = (wid >> 2) * 64;       // warp M offset (2 rows of warps)
    const int wn = (wid & 3) * 32;        // warp N offset (4 cols of warps)

    float acc[4][4][4];
    #pragma unroll
    for (int a = 0; a < 4; a++)
        #pragma unroll
        for (int b = 0; b < 4; b++)
            #pragma unroll
            for (int q = 0; q < 4; q++) acc[a][b][q] = 0.f;

    const __nv_bfloat16* Asegs[3] = {Ahi, Ahi, Alo};
    const __nv_bfloat16* Bsegs[3] = {Bhi, Blo, Bhi};

    // prologue: fill stages 0, 1 (both in segment 0)
    #pragma unroll
    for (int s = 0; s < 2; s++) {
        uint32_t smA = sb + s * STAGE_SZ;
        load_chunk(smA, smA + ABUF_SZ, Asegs[0], Bsegs[0], m0, n0, s * 64, tid);
    }

    const int ldrow = lane & 15;          // row within 16-row fragment
    const int ghalf = lane >> 4;          // 0/1 -> 16B granule half

    for (int c = 0; c < NCHUNKS; c++) {
        if (c < NCHUNKS - 1) { CP_WAIT1(); } else { CP_WAIT0(); }
        __syncthreads();     // stage c visible; all warps done computing c-1
        if (c + 2 < NCHUNKS) {
            int kt  = c + 2;
            int seg = kt >> 3;
            int kc  = (kt & 7) * 64;
            uint32_t dA = sb + (kt % 3) * STAGE_SZ;
            load_chunk(dA, dA + ABUF_SZ, Asegs[seg], Bsegs[seg], m0, n0, kc, tid);
        }
        uint32_t smA = sb + (c % 3) * STAGE_SZ;
        uint32_t smB = smA + ABUF_SZ;

        #pragma unroll
        for (int ks = 0; ks < 4; ks++) {
            uint32_t aF[4][4];
            uint32_t bF[4][2];
            int g = ks * 2 + ghalf;
            #pragma unroll
            for (int mi = 0; mi < 4; mi++) {
                int r = wm + mi * 16 + ldrow;
                LDSM_X4(aF[mi][0], aF[mi][1], aF[mi][2], aF[mi][3],
                        smA + sw_off(r, g));
            }
            #pragma unroll
            for (int nj = 0; nj < 2; nj++) {
                uint32_t r0, r1, r2, r3;
                int r = wn + nj * 16 + ldrow;
                LDSM_X4(r0, r1, r2, r3, smB + sw_off(r, g));
                bF[nj * 2 + 0][0] = r0; bF[nj * 2 + 0][1] = r2;
                bF[nj * 2 + 1][0] = r1; bF[nj * 2 + 1][1] = r3;
            }
            #pragma unroll
            for (int mi = 0; mi < 4; mi++)
                #pragma unroll
                for (int nb = 0; nb < 4; nb++)
                    MMA16816(acc[mi][nb], aF[mi], bF[nb]);
        }
    }

    // ---- epilogue -------------------------------------------------------
    if (mode == 0) {
        #pragma unroll
        for (int mi = 0; mi < 4; mi++) {
            int mlo = m0 + wm + mi * 16 + (lane >> 2);
            #pragma unroll
            for (int nb = 0; nb < 4; nb++) {
                int j = n0 + wn + nb * 8 + (lane & 3) * 2;
                float2 b2 = *reinterpret_cast<const float2*>(addend + j);
                float2 v0 = {acc[mi][nb][0] + b2.x, acc[mi][nb][1] + b2.y};
                float2 v1 = {acc[mi][nb][2] + b2.x, acc[mi][nb][3] + b2.y};
                *reinterpret_cast<float2*>(xw_out + (size_t)mlo * N_TOT + j) = v0;
                *reinterpret_cast<float2*>(xw_out + (size_t)(mlo + 8) * N_TOT + j) = v1;
            }
        }
    } else {
        const int p = lane & 1;
        #pragma unroll
        for (int mi = 0; mi < 4; mi++) {
            int m = m0 + wm + mi * 16 + (lane >> 2) + p * 8;
            float nm = node_mask[m];
            #pragma unroll
            for (int nb = 0; nb < 4; nb++) {
                float* a = acc[mi][nb];
                float o0 = __shfl_xor_sync(0xffffffffu, a[0], 1);
                float o1 = __shfl_xor_sync(0xffffffffu, a[1], 1);
                float o2 = __shfl_xor_sync(0xffffffffu, a[2], 1);
                float o3 = __shfl_xor_sync(0xffffffffu, a[3], 1);
                int dg = ((n0 + wn + nb * 8) >> 2) + ((lane & 3) >> 1);
                float vi, vo, vf, vg;
                if (p == 0) { vi = a[0]; vo = a[1]; vf = o0; vg = o1; }
                else        { vi = o2;  vo = o3;  vf = a[2]; vg = a[3]; }
                float4 xv = *reinterpret_cast<const float4*>(
                    addend + (size_t)m * N_TOT + dg * 4);
                float ig = sigf(vi + xv.x);
                float og = sigf(vo + xv.y);
                float fg = sigf(vf + xv.z);
                float gg = tanhf(vg + xv.w);
                float cv = c_in[(size_t)m * DDIM + dg];
                float cn = (fg * cv + ig * gg) * nm;
                c_out[(size_t)m * DDIM + dg] = cn;
                h_out[(size_t)m * DDIM + dg] = og * tanhf(cn) * nm;
            }
        }
    }
}

// ---------------- launch ----------------------------------------------------
extern "C" void kernel_launch(void* const* d_in, const int* in_sizes, int n_in,
                              void* d_out, int out_size)
{
    const float* h0        = (const float*)d_in[0];
    const float* c0        = (const float*)d_in[1];
    const float* x_in      = (const float*)d_in[2];
    const float* x_out     = (const float*)d_in[3];
    const float* W_in      = (const float*)d_in[4];
    const float* U_in      = (const float*)d_in[5];
    const float* W_out     = (const float*)d_in[6];
    const float* U_out     = (const float*)d_in[7];
    const float* bias      = (const float*)d_in[8];
    const float* in_mask   = (const float*)d_in[9];
    const float* out_mask  = (const float*)d_in[10];
    const float* node_mask = (const float*)d_in[11];
    const int*   in_nodes  = (const int*)d_in[12];
    const int*   out_nodes = (const int*)d_in[13];

    __nv_bfloat16 *Bwh, *Bwl, *Buh, *Bul, *Axh, *Axl, *Ahh, *Ahl;
    float *xw, *hbuf, *cbuf, *bi;
    cudaGetSymbolAddress((void**)&Bwh, g_Bw_hi);
    cudaGetSymbolAddress((void**)&Bwl, g_Bw_lo);
    cudaGetSymbolAddress((void**)&Buh, g_Bu_hi);
    cudaGetSymbolAddress((void**)&Bul, g_Bu_lo);
    cudaGetSymbolAddress((void**)&Axh, g_Ax_hi);
    cudaGetSymbolAddress((void**)&Axl, g_Ax_lo);
    cudaGetSymbolAddress((void**)&Ahh, g_Ah_hi);
    cudaGetSymbolAddress((void**)&Ahl, g_Ah_lo);
    cudaGetSymbolAddress((void**)&xw,   g_xw);
    cudaGetSymbolAddress((void**)&hbuf, g_h);
    cudaGetSymbolAddress((void**)&cbuf, g_c);
    cudaGetSymbolAddress((void**)&bi,   g_bias);

    float* out = (float*)d_out;

    cudaFuncSetAttribute(gemm_fused_kernel,
                         cudaFuncAttributeMaxDynamicSharedMemorySize, SMEM_REQ);

    pack_w_kernel<<<(N_TOT * K_HALF + 255) / 256, 256>>>(W_in, W_out, Bwh, Bwl);
    pack_w_kernel<<<(N_TOT * K_HALF + 255) / 256, 256>>>(U_in, U_out, Buh, Bul);
    pack_bias_kernel<<<4, 256>>>(bias, bi);
    convert_x_kernel<<<(M_TOT * 128 + 255) / 256, 256>>>(x_in, x_out, Axh, Axl);

    dim3 ggrid(N_TOT / 128, M_TOT / 128);   // (8, 64)

    // layer-invariant xw = x @ W + bias  (interleaved columns)
    gemm_fused_kernel<<<ggrid, 256, SMEM_REQ>>>(
        Axh, Axl, Bwh, Bwl, bi, nullptr, nullptr, nullptr, nullptr, xw, 0);

    for (int layer = 0; layer < LLAYERS; layer++) {
        const float* hsrc = (layer == 0) ? h0 : hbuf;
        const float* csrc = (layer == 0) ? c0 : cbuf;
        float* hdst = (layer == LLAYERS - 1) ? out : hbuf;

        gather_kernel<<<M_TOT / 4, 256>>>(hsrc, in_nodes, in_mask,
                                          out_nodes, out_mask, node_mask,
                                          Ahh, Ahl);
        gemm_fused_kernel<<<ggrid, 256, SMEM_REQ>>>(
            Ahh, Ahl, Buh, Bul, xw, csrc, node_mask, cbuf, hdst, nullptr, 1);
    }
}

// round 6
// speedup vs baseline: 2.4087x; 1.2247x over previous
#include <cuda_runtime.h>
#include <cuda_fp16.h>
#include <cstdint>

// Fixed problem shape: B=8, N=1024, K=16, D=256, L=3
#define M_TOT   8192
#define DDIM    256
#define KNBR    16
#define LLAYERS 3
#define K_HALF  512          // packed activation width ([in|out] halves)
#define N_TOT   1024         // 4 gates x 256, interleaved as j = 4*d+g
#define NCHUNKS 16           // 2 segments (A*Bhi, A*Blo) x 8 chunks of k=64

// ---------------- device scratch (static; no runtime alloc) ----------------
__device__ __align__(256) __half g_Bw_hi[N_TOT * K_HALF];
__device__ __align__(256) __half g_Bw_lo[N_TOT * K_HALF];
__device__ __align__(256) __half g_Bu_hi[N_TOT * K_HALF];
__device__ __align__(256) __half g_Bu_lo[N_TOT * K_HALF];
__device__ __align__(256) __half g_Ax[M_TOT * K_HALF];
__device__ __align__(256) __half g_Ah[M_TOT * K_HALF];
__device__ __align__(256) float g_xw[M_TOT * N_TOT];     // interleaved cols
__device__ __align__(256) float g_h[M_TOT * DDIM];
__device__ __align__(256) float g_c[M_TOT * DDIM];
__device__ __align__(256) float g_bias[N_TOT];

// ---------------- PTX helpers ----------------------------------------------
__device__ __forceinline__ uint32_t smem_u32(const void* p) {
    uint32_t a;
    asm("{ .reg .u64 t; cvta.to.shared.u64 t, %1; cvt.u32.u64 %0, t; }"
        : "=r"(a) : "l"(p));
    return a;
}
__device__ __forceinline__ void cp_async16(uint32_t dst, const void* src) {
    asm volatile("cp.async.cg.shared.global [%0], [%1], 16;\n"
                 :: "r"(dst), "l"(src));
}
#define CP_COMMIT() asm volatile("cp.async.commit_group;" ::: "memory")
#define CP_WAIT1()  asm volatile("cp.async.wait_group 1;" ::: "memory")
#define CP_WAIT0()  asm volatile("cp.async.wait_group 0;" ::: "memory")

#define LDSM_X4(r0, r1, r2, r3, addr) \
    asm volatile("ldmatrix.sync.aligned.m8n8.x4.shared.b16 {%0,%1,%2,%3}, [%4];" \
        : "=r"(r0), "=r"(r1), "=r"(r2), "=r"(r3) : "r"(addr))

#define MMA16816(d, a, b) \
    asm volatile("mma.sync.aligned.m16n8k16.row.col.f32.f16.f16.f32 " \
        "{%0,%1,%2,%3}, {%4,%5,%6,%7}, {%8,%9}, {%0,%1,%2,%3};" \
        : "+f"((d)[0]), "+f"((d)[1]), "+f"((d)[2]), "+f"((d)[3]) \
        : "r"((a)[0]), "r"((a)[1]), "r"((a)[2]), "r"((a)[3]), \
          "r"((b)[0]), "r"((b)[1]))

// ---------------- fp16 store helper -----------------------------------------
__device__ __forceinline__ void store4_half(__half* p, float4 v) {
    __half2* p2 = reinterpret_cast<__half2*>(p);
    p2[0] = __floats2half2_rn(v.x, v.y);
    p2[1] = __floats2half2_rn(v.z, v.w);
}

// ---------------- weight pack: Bt[j][e], j = 4*d+g, fp16 hi/lo --------------
__global__ void pack_w_kernel(const float* __restrict__ Wa,
                              const float* __restrict__ Wb,
                              __half* __restrict__ Bhi,
                              __half* __restrict__ Blo)
{
    int idx = blockIdx.x * blockDim.x + threadIdx.x;   // 1024*512
    if (idx >= N_TOT * K_HALF) return;
    int j = idx >> 9;          // 0..1023 interleaved col
    int e = idx & 511;         // 0..511
    int d = j >> 2;
    int g = j & 3;
    float v = (e < DDIM) ? Wa[g * DDIM * DDIM + e * DDIM + d]
                         : Wb[g * DDIM * DDIM + (e - DDIM) * DDIM + d];
    __half h = __float2half_rn(v);
    Bhi[idx] = h;
    Blo[idx] = __float2half_rn(v - __half2float(h));
}

__global__ void pack_bias_kernel(const float* __restrict__ b, float* __restrict__ bi)
{
    int j = blockIdx.x * blockDim.x + threadIdx.x;
    if (j >= N_TOT) return;
    bi[j] = b[(j & 3) * DDIM + (j >> 2)];
}

// ---------------- x conversion: Ax[m][0:256]=x_in, [256:512]=x_out ----------
__global__ __launch_bounds__(256) void convert_x_kernel(
    const float* __restrict__ x_in, const float* __restrict__ x_out,
    __half* __restrict__ A)
{
    int idx4 = blockIdx.x * blockDim.x + threadIdx.x;   // 8192*128
    if (idx4 >= M_TOT * 128) return;
    int m = idx4 >> 7;
    int c4 = idx4 & 127;
    float4 v = (c4 < 64)
        ? *reinterpret_cast<const float4*>(x_in + (size_t)m * DDIM + c4 * 4)
        : *reinterpret_cast<const float4*>(x_out + (size_t)m * DDIM + (c4 - 64) * 4);
    store4_half(A + (size_t)m * K_HALF + c4 * 4, v);
}

// ---------------- gather-aggregate -> fp16 packed activations --------------
__global__ __launch_bounds__(256) void gather_kernel(
    const float* __restrict__ h,
    const int*   __restrict__ in_nodes,  const float* __restrict__ in_mask,
    const int*   __restrict__ out_nodes, const float* __restrict__ out_mask,
    const float* __restrict__ node_mask,
    __half* __restrict__ A)
{
    int m  = blockIdx.x * 4 + (threadIdx.x >> 6);
    int d4 = threadIdx.x & 63;
    float nm = node_mask[m];
    __half* hin  = A + (size_t)m * K_HALF + 4 * d4;
    __half* hout = hin + DDIM;
    float4 ai = {0.f, 0.f, 0.f, 0.f};
    float4 ao = {0.f, 0.f, 0.f, 0.f};
    if (nm != 0.f) {
        const float* hb = h + (size_t)(m >> 10) * 1024 * DDIM;
        int base = m * KNBR;
        #pragma unroll
        for (int k = 0; k < KNBR; k++) {
            int   ni = in_nodes[base + k];
            float wi = in_mask [base + k];
            float4 v = *(reinterpret_cast<const float4*>(hb + (size_t)ni * DDIM) + d4);
            ai.x += wi * v.x; ai.y += wi * v.y; ai.z += wi * v.z; ai.w += wi * v.w;
            int   no = out_nodes[base + k];
            float wo = out_mask [base + k];
            float4 u = *(reinterpret_cast<const float4*>(hb + (size_t)no * DDIM) + d4);
            ao.x += wo * u.x; ao.y += wo * u.y; ao.z += wo * u.z; ao.w += wo * u.w;
        }
        ai.x *= nm; ai.y *= nm; ai.z *= nm; ai.w *= nm;
        ao.x *= nm; ao.y *= nm; ao.z *= nm; ao.w *= nm;
    }
    store4_half(hin, ai);
    store4_half(hout, ao);
}

// ---------------- HMMA GEMM + fused epilogue -------------------------------
// CTA tile 128x128, warp tile 64x32, mma.sync m16n8k16 fp16.
// K' = 1024 (A*Bhi then A*Blo), chunks of 64, 3-stage cp.async pipeline,
// ONE __syncthreads per chunk, XOR-swizzled 128B rows (no padding).
#define ABUF_SZ  (128 * 128)          // 16 KB (128 rows x 128B)
#define STAGE_SZ (2 * ABUF_SZ)        // 32 KB
#define SMEM_REQ (3 * STAGE_SZ)       // 96 KB

__device__ __forceinline__ float sigf(float x) { return 1.f / (1.f + __expf(-x)); }

// swizzled smem byte offset for (row r, 16B-granule g)
__device__ __forceinline__ uint32_t sw_off(int r, int g) {
    return (uint32_t)(r * 128 + ((g ^ (r & 7)) << 4));
}

__device__ __forceinline__ void load_chunk(
    uint32_t smA, uint32_t smB,
    const __half* Aseg, const __half* Bseg,
    int m0, int n0, int kc, int tid)
{
    const char* Ab = reinterpret_cast<const char*>(Aseg) +
                     ((size_t)m0 * K_HALF + kc) * 2;
    const char* Bb = reinterpret_cast<const char*>(Bseg) +
                     ((size_t)n0 * K_HALF + kc) * 2;
    #pragma unroll
    for (int i = 0; i < 4; i++) {
        int idx = tid + i * 256;           // 0..1023
        int r = idx >> 3;                  // 0..127
        int g = idx & 7;                   // 16B granule
        size_t go = (size_t)r * (K_HALF * 2) + g * 16;
        cp_async16(smA + sw_off(r, g), Ab + go);
        cp_async16(smB + sw_off(r, g), Bb + go);
    }
    CP_COMMIT();
}

__global__ __launch_bounds__(256, 2) void gemm_fused_kernel(
    const __half* __restrict__ A,
    const __half* __restrict__ Bhi, const __half* __restrict__ Blo,
    const float* __restrict__ addend,      // bias (mode0) or xw (mode1)
    const float* __restrict__ c_in, const float* __restrict__ node_mask,
    float* __restrict__ c_out, float* __restrict__ h_out,
    float* __restrict__ xw_out, int mode)
{
    extern __shared__ __align__(128) char smem_raw[];
    const uint32_t sb = smem_u32(smem_raw);
    const int tid  = threadIdx.x;
    const int wid  = tid >> 5;
    const int lane = tid & 31;
    const int m0 = blockIdx.y * 128;
    const int n0 = blockIdx.x * 128;
    const int wm = (wid >> 2) * 64;       // warp M offset (2 rows of warps)
    const int wn = (wid & 3) * 32;        // warp N offset (4 cols of warps)

    float acc[4][4][4];
    #pragma unroll
    for (int a = 0; a < 4; a++)
        #pragma unroll
        for (int b = 0; b < 4; b++)
            #pragma unroll
            for (int q = 0; q < 4; q++) acc[a][b][q] = 0.f;

    const __half* Bsegs[2] = {Bhi, Blo};

    // prologue: fill stages 0, 1 (both in segment 0)
    #pragma unroll
    for (int s = 0; s < 2; s++) {
        uint32_t smA = sb + s * STAGE_SZ;
        load_chunk(smA, smA + ABUF_SZ, A, Bsegs[0], m0, n0, s * 64, tid);
    }

    const int ldrow = lane & 15;          // row within 16-row fragment
    const int ghalf = lane >> 4;          // 0/1 -> 16B granule half

    for (int c = 0; c < NCHUNKS; c++) {
        if (c < NCHUNKS - 1) { CP_WAIT1(); } else { CP_WAIT0(); }
        __syncthreads();     // stage c visible; all warps done computing c-1
        if (c + 2 < NCHUNKS) {
            int kt  = c + 2;
            int seg = kt >> 3;
            int kc  = (kt & 7) * 64;
            uint32_t dA = sb + (kt % 3) * STAGE_SZ;
            load_chunk(dA, dA + ABUF_SZ, A, Bsegs[seg], m0, n0, kc, tid);
        }
        uint32_t smA = sb + (c % 3) * STAGE_SZ;
        uint32_t smB = smA + ABUF_SZ;

        #pragma unroll
        for (int ks = 0; ks < 4; ks++) {
            uint32_t aF[4][4];
            uint32_t bF[4][2];
            int g = ks * 2 + ghalf;
            #pragma unroll
            for (int mi = 0; mi < 4; mi++) {
                int r = wm + mi * 16 + ldrow;
                LDSM_X4(aF[mi][0], aF[mi][1], aF[mi][2], aF[mi][3],
                        smA + sw_off(r, g));
            }
            #pragma unroll
            for (int nj = 0; nj < 2; nj++) {
                uint32_t r0, r1, r2, r3;
                int r = wn + nj * 16 + ldrow;
                LDSM_X4(r0, r1, r2, r3, smB + sw_off(r, g));
                bF[nj * 2 + 0][0] = r0; bF[nj * 2 + 0][1] = r2;
                bF[nj * 2 + 1][0] = r1; bF[nj * 2 + 1][1] = r3;
            }
            #pragma unroll
            for (int mi = 0; mi < 4; mi++)
                #pragma unroll
                for (int nb = 0; nb < 4; nb++)
                    MMA16816(acc[mi][nb], aF[mi], bF[nb]);
        }
    }

    // ---- epilogue -------------------------------------------------------
    if (mode == 0) {
        #pragma unroll
        for (int mi = 0; mi < 4; mi++) {
            int mlo = m0 + wm + mi * 16 + (lane >> 2);
            #pragma unroll
            for (int nb = 0; nb < 4; nb++) {
                int j = n0 + wn + nb * 8 + (lane & 3) * 2;
                float2 b2 = *reinterpret_cast<const float2*>(addend + j);
                float2 v0 = {acc[mi][nb][0] + b2.x, acc[mi][nb][1] + b2.y};
                float2 v1 = {acc[mi][nb][2] + b2.x, acc[mi][nb][3] + b2.y};
                *reinterpret_cast<float2*>(xw_out + (size_t)mlo * N_TOT + j) = v0;
                *reinterpret_cast<float2*>(xw_out + (size_t)(mlo + 8) * N_TOT + j) = v1;
            }
        }
    } else {
        const int p = lane & 1;
        #pragma unroll
        for (int mi = 0; mi < 4; mi++) {
            int m = m0 + wm + mi * 16 + (lane >> 2) + p * 8;
            float nm = node_mask[m];
            #pragma unroll
            for (int nb = 0; nb < 4; nb++) {
                float* a = acc[mi][nb];
                float o0 = __shfl_xor_sync(0xffffffffu, a[0], 1);
                float o1 = __shfl_xor_sync(0xffffffffu, a[1], 1);
                float o2 = __shfl_xor_sync(0xffffffffu, a[2], 1);
                float o3 = __shfl_xor_sync(0xffffffffu, a[3], 1);
                int dg = ((n0 + wn + nb * 8) >> 2) + ((lane & 3) >> 1);
                float vi, vo, vf, vg;
                if (p == 0) { vi = a[0]; vo = a[1]; vf = o0; vg = o1; }
                else        { vi = o2;  vo = o3;  vf = a[2]; vg = a[3]; }
                float4 xv = *reinterpret_cast<const float4*>(
                    addend + (size_t)m * N_TOT + dg * 4);
                float ig = sigf(vi + xv.x);
                float og = sigf(vo + xv.y);
                float fg = sigf(vf + xv.z);
                float gg = tanhf(vg + xv.w);
                float cv = c_in[(size_t)m * DDIM + dg];
                float cn = (fg * cv + ig * gg) * nm;
                c_out[(size_t)m * DDIM + dg] = cn;
                h_out[(size_t)m * DDIM + dg] = og * tanhf(cn) * nm;
            }
        }
    }
}

// ---------------- launch ----------------------------------------------------
extern "C" void kernel_launch(void* const* d_in, const int* in_sizes, int n_in,
                              void* d_out, int out_size)
{
    const float* h0        = (const float*)d_in[0];
    const float* c0        = (const float*)d_in[1];
    const float* x_in      = (const float*)d_in[2];
    const float* x_out     = (const float*)d_in[3];
    const float* W_in      = (const float*)d_in[4];
    const float* U_in      = (const float*)d_in[5];
    const float* W_out     = (const float*)d_in[6];
    const float* U_out     = (const float*)d_in[7];
    const float* bias      = (const float*)d_in[8];
    const float* in_mask   = (const float*)d_in[9];
    const float* out_mask  = (const float*)d_in[10];
    const float* node_mask = (const float*)d_in[11];
    const int*   in_nodes  = (const int*)d_in[12];
    const int*   out_nodes = (const int*)d_in[13];

    __half *Bwh, *Bwl, *Buh, *Bul, *Ax, *Ah;
    float *xw, *hbuf, *cbuf, *bi;
    cudaGetSymbolAddress((void**)&Bwh, g_Bw_hi);
    cudaGetSymbolAddress((void**)&Bwl, g_Bw_lo);
    cudaGetSymbolAddress((void**)&Buh, g_Bu_hi);
    cudaGetSymbolAddress((void**)&Bul, g_Bu_lo);
    cudaGetSymbolAddress((void**)&Ax,  g_Ax);
    cudaGetSymbolAddress((void**)&Ah,  g_Ah);
    cudaGetSymbolAddress((void**)&xw,   g_xw);
    cudaGetSymbolAddress((void**)&hbuf, g_h);
    cudaGetSymbolAddress((void**)&cbuf, g_c);
    cudaGetSymbolAddress((void**)&bi,   g_bias);

    float* out = (float*)d_out;

    cudaFuncSetAttribute(gemm_fused_kernel,
                         cudaFuncAttributeMaxDynamicSharedMemorySize, SMEM_REQ);

    pack_w_kernel<<<(N_TOT * K_HALF + 255) / 256, 256>>>(W_in, W_out, Bwh, Bwl);
    pack_w_kernel<<<(N_TOT * K_HALF + 255) / 256, 256>>>(U_in, U_out, Buh, Bul);
    pack_bias_kernel<<<4, 256>>>(bias, bi);
    convert_x_kernel<<<(M_TOT * 128 + 255) / 256, 256>>>(x_in, x_out, Ax);

    dim3 ggrid(N_TOT / 128, M_TOT / 128);   // (8, 64)

    // layer-invariant xw = x @ W + bias  (interleaved columns)
    gemm_fused_kernel<<<ggrid, 256, SMEM_REQ>>>(
        Ax, Bwh, Bwl, bi, nullptr, nullptr, nullptr, nullptr, xw, 0);

    for (int layer = 0; layer < LLAYERS; layer++) {
        const float* hsrc = (layer == 0) ? h0 : hbuf;
        const float* csrc = (layer == 0) ? c0 : cbuf;
        float* hdst = (layer == LLAYERS - 1) ? out : hbuf;

        gather_kernel<<<M_TOT / 4, 256>>>(hsrc, in_nodes, in_mask,
                                          out_nodes, out_mask, node_mask, Ah);
        gemm_fused_kernel<<<ggrid, 256, SMEM_REQ>>>(
            Ah, Buh, Bul, xw, csrc, node_mask, cbuf, hdst, nullptr, 1);
    }
}

// round 7
// speedup vs baseline: 2.7769x; 1.1529x over previous
#include <cuda_runtime.h>
#include <cuda_fp16.h>
#include <cstdint>

// Fixed problem shape: B=8, N=1024, K=16, D=256, L=3
#define M_TOT   8192
#define DDIM    256
#define KNBR    16
#define LLAYERS 3
#define K_HALF  512          // packed activation width ([in|out] halves)
#define N_TOT   1024         // 4 gates x 256, interleaved as j = 4*d+g
#define NCHUNKS 16           // 2 segments (A*Bhi, A*Blo) x 8 chunks of k=64

// ---------------- device scratch (static; no runtime alloc) ----------------
__device__ __align__(256) __half g_Bw_hi[N_TOT * K_HALF];
__device__ __align__(256) __half g_Bw_lo[N_TOT * K_HALF];
__device__ __align__(256) __half g_Bu_hi[N_TOT * K_HALF];
__device__ __align__(256) __half g_Bu_lo[N_TOT * K_HALF];
__device__ __align__(256) __half g_Ax[M_TOT * K_HALF];
__device__ __align__(256) __half g_Ah[M_TOT * K_HALF];
__device__ __align__(256) float g_xw[M_TOT * N_TOT];     // interleaved cols
__device__ __align__(256) float g_h[M_TOT * DDIM];
__device__ __align__(256) float g_c[M_TOT * DDIM];
__device__ __align__(256) float g_bias[N_TOT];

// ---------------- PTX helpers ----------------------------------------------
__device__ __forceinline__ uint32_t smem_u32(const void* p) {
    uint32_t a;
    asm("{ .reg .u64 t; cvta.to.shared.u64 t, %1; cvt.u32.u64 %0, t; }"
        : "=r"(a) : "l"(p));
    return a;
}
__device__ __forceinline__ void cp_async16(uint32_t dst, const void* src) {
    asm volatile("cp.async.cg.shared.global [%0], [%1], 16;\n"
                 :: "r"(dst), "l"(src));
}
#define CP_COMMIT() asm volatile("cp.async.commit_group;" ::: "memory")
#define CP_WAIT1()  asm volatile("cp.async.wait_group 1;" ::: "memory")
#define CP_WAIT0()  asm volatile("cp.async.wait_group 0;" ::: "memory")

#define LDSM_X4(r0, r1, r2, r3, addr) \
    asm volatile("ldmatrix.sync.aligned.m8n8.x4.shared.b16 {%0,%1,%2,%3}, [%4];" \
        : "=r"(r0), "=r"(r1), "=r"(r2), "=r"(r3) : "r"(addr))

#define MMA16816(d, a, b) \
    asm volatile("mma.sync.aligned.m16n8k16.row.col.f32.f16.f16.f32 " \
        "{%0,%1,%2,%3}, {%4,%5,%6,%7}, {%8,%9}, {%0,%1,%2,%3};" \
        : "+f"((d)[0]), "+f"((d)[1]), "+f"((d)[2]), "+f"((d)[3]) \
        : "r"((a)[0]), "r"((a)[1]), "r"((a)[2]), "r"((a)[3]), \
          "r"((b)[0]), "r"((b)[1]))

// ---------------- fp16 store helper -----------------------------------------
__device__ __forceinline__ void store4_half(__half* p, float4 v) {
    __half2* p2 = reinterpret_cast<__half2*>(p);
    p2[0] = __floats2half2_rn(v.x, v.y);
    p2[1] = __floats2half2_rn(v.z, v.w);
}

// ---------------- weight pack: Bt[j][e], j = 4*d+g, fp16 hi/lo --------------
__global__ void pack_w_kernel(const float* __restrict__ Wa,
                              const float* __restrict__ Wb,
                              __half* __restrict__ Bhi,
                              __half* __restrict__ Blo)
{
    int idx = blockIdx.x * blockDim.x + threadIdx.x;   // 1024*512
    if (idx >= N_TOT * K_HALF) return;
    int j = idx >> 9;          // 0..1023 interleaved col
    int e = idx & 511;         // 0..511
    int d = j >> 2;
    int g = j & 3;
    float v = (e < DDIM) ? Wa[g * DDIM * DDIM + e * DDIM + d]
                         : Wb[g * DDIM * DDIM + (e - DDIM) * DDIM + d];
    __half h = __float2half_rn(v);
    Bhi[idx] = h;
    Blo[idx] = __float2half_rn(v - __half2float(h));
}

__global__ void pack_bias_kernel(const float* __restrict__ b, float* __restrict__ bi)
{
    int j = blockIdx.x * blockDim.x + threadIdx.x;
    if (j >= N_TOT) return;
    bi[j] = b[(j & 3) * DDIM + (j >> 2)];
}

// ---------------- x conversion: Ax[m][0:256]=x_in, [256:512]=x_out ----------
__global__ __launch_bounds__(256) void convert_x_kernel(
    const float* __restrict__ x_in, const float* __restrict__ x_out,
    __half* __restrict__ A)
{
    int idx4 = blockIdx.x * blockDim.x + threadIdx.x;   // 8192*128
    if (idx4 >= M_TOT * 128) return;
    int m = idx4 >> 7;
    int c4 = idx4 & 127;
    float4 v = (c4 < 64)
        ? *reinterpret_cast<const float4*>(x_in + (size_t)m * DDIM + c4 * 4)
        : *reinterpret_cast<const float4*>(x_out + (size_t)m * DDIM + (c4 - 64) * 4);
    store4_half(A + (size_t)m * K_HALF + c4 * 4, v);
}

// ---------------- gather-aggregate -> fp16 packed activations --------------
__global__ __launch_bounds__(256) void gather_kernel(
    const float* __restrict__ h,
    const int*   __restrict__ in_nodes,  const float* __restrict__ in_mask,
    const int*   __restrict__ out_nodes, const float* __restrict__ out_mask,
    const float* __restrict__ node_mask,
    __half* __restrict__ A)
{
    int m  = blockIdx.x * 4 + (threadIdx.x >> 6);
    int d4 = threadIdx.x & 63;
    float nm = node_mask[m];
    __half* hin  = A + (size_t)m * K_HALF + 4 * d4;
    __half* hout = hin + DDIM;
    float4 ai = {0.f, 0.f, 0.f, 0.f};
    float4 ao = {0.f, 0.f, 0.f, 0.f};
    if (nm != 0.f) {
        const float* hb = h + (size_t)(m >> 10) * 1024 * DDIM;
        int base = m * KNBR;
        #pragma unroll
        for (int k = 0; k < KNBR; k++) {
            int   ni = in_nodes[base + k];
            float wi = in_mask [base + k];
            float4 v = *(reinterpret_cast<const float4*>(hb + (size_t)ni * DDIM) + d4);
            ai.x += wi * v.x; ai.y += wi * v.y; ai.z += wi * v.z; ai.w += wi * v.w;
            int   no = out_nodes[base + k];
            float wo = out_mask [base + k];
            float4 u = *(reinterpret_cast<const float4*>(hb + (size_t)no * DDIM) + d4);
            ao.x += wo * u.x; ao.y += wo * u.y; ao.z += wo * u.z; ao.w += wo * u.w;
        }
        ai.x *= nm; ai.y *= nm; ai.z *= nm; ai.w *= nm;
        ao.x *= nm; ao.y *= nm; ao.z *= nm; ao.w *= nm;
    }
    store4_half(hin, ai);
    store4_half(hout, ao);
}

// ---------------- HMMA GEMM + fused epilogue -------------------------------
// CTA tile 128x128, warp tile 64x32, mma.sync m16n8k16 fp16.
// K' = 1024 (A*Bhi then A*Blo), chunks of 64, 3-stage cp.async pipeline.
// Accumulator is initialized from the addend (bias / xw), so the addend
// DRAM reads overlap the pipeline-fill instead of serializing in the epilogue.
#define ABUF_SZ  (128 * 128)          // 16 KB (128 rows x 128B)
#define STAGE_SZ (2 * ABUF_SZ)        // 32 KB
#define SMEM_REQ (3 * STAGE_SZ)       // 96 KB

__device__ __forceinline__ float sigf(float x) { return 1.f / (1.f + __expf(-x)); }

// swizzled smem byte offset for (row r, 16B-granule g)
__device__ __forceinline__ uint32_t sw_off(int r, int g) {
    return (uint32_t)(r * 128 + ((g ^ (r & 7)) << 4));
}

__device__ __forceinline__ void load_chunk(
    uint32_t smA, uint32_t smB,
    const __half* Aseg, const __half* Bseg,
    int m0, int n0, int kc, int tid)
{
    const char* Ab = reinterpret_cast<const char*>(Aseg) +
                     ((size_t)m0 * K_HALF + kc) * 2;
    const char* Bb = reinterpret_cast<const char*>(Bseg) +
                     ((size_t)n0 * K_HALF + kc) * 2;
    #pragma unroll
    for (int i = 0; i < 4; i++) {
        int idx = tid + i * 256;           // 0..1023
        int r = idx >> 3;                  // 0..127
        int g = idx & 7;                   // 16B granule
        size_t go = (size_t)r * (K_HALF * 2) + g * 16;
        cp_async16(smA + sw_off(r, g), Ab + go);
        cp_async16(smB + sw_off(r, g), Bb + go);
    }
    CP_COMMIT();
}

__global__ __launch_bounds__(256, 2) void gemm_fused_kernel(
    const __half* __restrict__ A,
    const __half* __restrict__ Bhi, const __half* __restrict__ Blo,
    const float* __restrict__ addend,      // bias (mode0) or xw (mode1)
    const float* __restrict__ c_in, const float* __restrict__ node_mask,
    float* __restrict__ c_out, float* __restrict__ h_out,
    float* __restrict__ xw_out, int mode)
{
    extern __shared__ __align__(128) char smem_raw[];
    const uint32_t sb = smem_u32(smem_raw);
    const int tid  = threadIdx.x;
    const int wid  = tid >> 5;
    const int lane = tid & 31;
    const int m0 = blockIdx.y * 128;
    const int n0 = blockIdx.x * 128;
    const int wm = (wid >> 2) * 64;       // warp M offset (2 rows of warps)
    const int wn = (wid & 3) * 32;        // warp N offset (4 cols of warps)

    // ---- accumulator init from addend (overlaps pipeline fill) ----------
    float acc[4][4][4];
    if (mode == 0) {
        #pragma unroll
        for (int nb = 0; nb < 4; nb++) {
            int j = n0 + wn + nb * 8 + (lane & 3) * 2;
            float2 b2 = *reinterpret_cast<const float2*>(addend + j);
            #pragma unroll
            for (int mi = 0; mi < 4; mi++) {
                acc[mi][nb][0] = b2.x; acc[mi][nb][1] = b2.y;
                acc[mi][nb][2] = b2.x; acc[mi][nb][3] = b2.y;
            }
        }
    } else {
        #pragma unroll
        for (int mi = 0; mi < 4; mi++) {
            int mlo = m0 + wm + mi * 16 + (lane >> 2);
            #pragma unroll
            for (int nb = 0; nb < 4; nb++) {
                int j = n0 + wn + nb * 8 + (lane & 3) * 2;
                float2 v0 = *reinterpret_cast<const float2*>(
                    addend + (size_t)mlo * N_TOT + j);
                float2 v1 = *reinterpret_cast<const float2*>(
                    addend + (size_t)(mlo + 8) * N_TOT + j);
                acc[mi][nb][0] = v0.x; acc[mi][nb][1] = v0.y;
                acc[mi][nb][2] = v1.x; acc[mi][nb][3] = v1.y;
            }
        }
    }

    const __half* Bsegs[2] = {Bhi, Blo};

    // prologue: fill stages 0, 1 (both in segment 0)
    #pragma unroll
    for (int s = 0; s < 2; s++) {
        uint32_t smA = sb + s * STAGE_SZ;
        load_chunk(smA, smA + ABUF_SZ, A, Bsegs[0], m0, n0, s * 64, tid);
    }

    const int ldrow = lane & 15;          // row within 16-row fragment
    const int ghalf = lane >> 4;          // 0/1 -> 16B granule half

    for (int c = 0; c < NCHUNKS; c++) {
        if (c < NCHUNKS - 1) { CP_WAIT1(); } else { CP_WAIT0(); }
        __syncthreads();     // stage c visible; all warps done computing c-1
        if (c + 2 < NCHUNKS) {
            int kt  = c + 2;
            int seg = kt >> 3;
            int kc  = (kt & 7) * 64;
            uint32_t dA = sb + (kt % 3) * STAGE_SZ;
            load_chunk(dA, dA + ABUF_SZ, A, Bsegs[seg], m0, n0, kc, tid);
        }
        uint32_t smA = sb + (c % 3) * STAGE_SZ;
        uint32_t smB = smA + ABUF_SZ;

        #pragma unroll
        for (int ks = 0; ks < 4; ks++) {
            uint32_t aF[4][4];
            uint32_t bF[4][2];
            int g = ks * 2 + ghalf;
            #pragma unroll
            for (int mi = 0; mi < 4; mi++) {
                int r = wm + mi * 16 + ldrow;
                LDSM_X4(aF[mi][0], aF[mi][1], aF[mi][2], aF[mi][3],
                        smA + sw_off(r, g));
            }
            #pragma unroll
            for (int nj = 0; nj < 2; nj++) {
                uint32_t r0, r1, r2, r3;
                int r = wn + nj * 16 + ldrow;
                LDSM_X4(r0, r1, r2, r3, smB + sw_off(r, g));
                bF[nj * 2 + 0][0] = r0; bF[nj * 2 + 0][1] = r2;
                bF[nj * 2 + 1][0] = r1; bF[nj * 2 + 1][1] = r3;
            }
            #pragma unroll
            for (int mi = 0; mi < 4; mi++)
                #pragma unroll
                for (int nb = 0; nb < 4; nb++)
                    MMA16816(acc[mi][nb], aF[mi], bF[nb]);
        }
    }

    // ---- epilogue (addend already folded into acc) ----------------------
    if (mode == 0) {
        #pragma unroll
        for (int mi = 0; mi < 4; mi++) {
            int mlo = m0 + wm + mi * 16 + (lane >> 2);
            #pragma unroll
            for (int nb = 0; nb < 4; nb++) {
                int j = n0 + wn + nb * 8 + (lane & 3) * 2;
                float2 v0 = {acc[mi][nb][0], acc[mi][nb][1]};
                float2 v1 = {acc[mi][nb][2], acc[mi][nb][3]};
                *reinterpret_cast<float2*>(xw_out + (size_t)mlo * N_TOT + j) = v0;
                *reinterpret_cast<float2*>(xw_out + (size_t)(mlo + 8) * N_TOT + j) = v1;
            }
        }
    } else {
        const int p = lane & 1;
        #pragma unroll
        for (int mi = 0; mi < 4; mi++) {
            int m = m0 + wm + mi * 16 + (lane >> 2) + p * 8;
            float nm = node_mask[m];
            #pragma unroll
            for (int nb = 0; nb < 4; nb++) {
                float* a = acc[mi][nb];
                float o0 = __shfl_xor_sync(0xffffffffu, a[0], 1);
                float o1 = __shfl_xor_sync(0xffffffffu, a[1], 1);
                float o2 = __shfl_xor_sync(0xffffffffu, a[2], 1);
                float o3 = __shfl_xor_sync(0xffffffffu, a[3], 1);
                int dg = ((n0 + wn + nb * 8) >> 2) + ((lane & 3) >> 1);
                float vi, vo, vf, vg;
                if (p == 0) { vi = a[0]; vo = a[1]; vf = o0; vg = o1; }
                else        { vi = o2;  vo = o3;  vf = a[2]; vg = a[3]; }
                float ig = sigf(vi);
                float og = sigf(vo);
                float fg = sigf(vf);
                float gg = tanhf(vg);
                float cv = c_in[(size_t)m * DDIM + dg];
                float cn = (fg * cv + ig * gg) * nm;
                c_out[(size_t)m * DDIM + dg] = cn;
                h_out[(size_t)m * DDIM + dg] = og * tanhf(cn) * nm;
            }
        }
    }
}

// ---------------- launch ----------------------------------------------------
extern "C" void kernel_launch(void* const* d_in, const int* in_sizes, int n_in,
                              void* d_out, int out_size)
{
    const float* h0        = (const float*)d_in[0];
    const float* c0        = (const float*)d_in[1];
    const float* x_in      = (const float*)d_in[2];
    const float* x_out     = (const float*)d_in[3];
    const float* W_in      = (const float*)d_in[4];
    const float* U_in      = (const float*)d_in[5];
    const float* W_out     = (const float*)d_in[6];
    const float* U_out     = (const float*)d_in[7];
    const float* bias      = (const float*)d_in[8];
    const float* in_mask   = (const float*)d_in[9];
    const float* out_mask  = (const float*)d_in[10];
    const float* node_mask = (const float*)d_in[11];
    const int*   in_nodes  = (const int*)d_in[12];
    const int*   out_nodes = (const int*)d_in[13];

    __half *Bwh, *Bwl, *Buh, *Bul, *Ax, *Ah;
    float *xw, *hbuf, *cbuf, *bi;
    cudaGetSymbolAddress((void**)&Bwh, g_Bw_hi);
    cudaGetSymbolAddress((void**)&Bwl, g_Bw_lo);
    cudaGetSymbolAddress((void**)&Buh, g_Bu_hi);
    cudaGetSymbolAddress((void**)&Bul, g_Bu_lo);
    cudaGetSymbolAddress((void**)&Ax,  g_Ax);
    cudaGetSymbolAddress((void**)&Ah,  g_Ah);
    cudaGetSymbolAddress((void**)&xw,   g_xw);
    cudaGetSymbolAddress((void**)&hbuf, g_h);
    cudaGetSymbolAddress((void**)&cbuf, g_c);
    cudaGetSymbolAddress((void**)&bi,   g_bias);

    float* out = (float*)d_out;

    cudaFuncSetAttribute(gemm_fused_kernel,
                         cudaFuncAttributeMaxDynamicSharedMemorySize, SMEM_REQ);

    pack_w_kernel<<<(N_TOT * K_HALF + 255) / 256, 256>>>(W_in, W_out, Bwh, Bwl);
    pack_w_kernel<<<(N_TOT * K_HALF + 255) / 256, 256>>>(U_in, U_out, Buh, Bul);
    pack_bias_kernel<<<4, 256>>>(bias, bi);
    convert_x_kernel<<<(M_TOT * 128 + 255) / 256, 256>>>(x_in, x_out, Ax);

    dim3 ggrid(N_TOT / 128, M_TOT / 128);   // (8, 64)

    // layer-invariant xw = x @ W + bias  (interleaved columns)
    gemm_fused_kernel<<<ggrid, 256, SMEM_REQ>>>(
        Ax, Bwh, Bwl, bi, nullptr, nullptr, nullptr, nullptr, xw, 0);

    for (int layer = 0; layer < LLAYERS; layer++) {
        const float* hsrc = (layer == 0) ? h0 : hbuf;
        const float* csrc = (layer == 0) ? c0 : cbuf;
        float* hdst = (layer == LLAYERS - 1) ? out : hbuf;

        gather_kernel<<<M_TOT / 4, 256>>>(hsrc, in_nodes, in_mask,
                                          out_nodes, out_mask, node_mask, Ah);
        gemm_fused_kernel<<<ggrid, 256, SMEM_REQ>>>(
            Ah, Buh, Bul, xw, csrc, node_mask, cbuf, hdst, nullptr, 1);
    }
}

// round 8
// speedup vs baseline: 3.8912x; 1.4013x over previous
#include <cuda_runtime.h>
#include <cuda_fp16.h>
#include <cstdint>

// Fixed problem shape: B=8, N=1024, K=16, D=256, L=3
#define M_TOT   8192
#define DDIM    256
#define KNBR    16
#define LLAYERS 3
#define K_HALF  512          // packed activation width ([in|out] halves)
#define N_TOT   1024         // 4 gates x 256, interleaved as j = 4*d+g
#define NCHUNKS 8            // K' = 512, chunks of k=64

// ---------------- device scratch (static; no runtime alloc) ----------------
__device__ __align__(256) __half g_Bw[N_TOT * K_HALF];
__device__ __align__(256) __half g_Bu[N_TOT * K_HALF];
__device__ __align__(256) __half g_Ax[M_TOT * K_HALF];
__device__ __align__(256) __half g_Ah[M_TOT * K_HALF];
__device__ __align__(256) float g_xw[M_TOT * N_TOT];     // interleaved cols
__device__ __align__(256) float g_h[M_TOT * DDIM];
__device__ __align__(256) float g_c[M_TOT * DDIM];
__device__ __align__(256) float g_bias[N_TOT];

// ---------------- PTX helpers ----------------------------------------------
__device__ __forceinline__ uint32_t smem_u32(const void* p) {
    uint32_t a;
    asm("{ .reg .u64 t; cvta.to.shared.u64 t, %1; cvt.u32.u64 %0, t; }"
        : "=r"(a) : "l"(p));
    return a;
}
__device__ __forceinline__ void cp_async16(uint32_t dst, const void* src) {
    asm volatile("cp.async.cg.shared.global [%0], [%1], 16;\n"
                 :: "r"(dst), "l"(src));
}
#define CP_COMMIT() asm volatile("cp.async.commit_group;" ::: "memory")
#define CP_WAIT1()  asm volatile("cp.async.wait_group 1;" ::: "memory")
#define CP_WAIT0()  asm volatile("cp.async.wait_group 0;" ::: "memory")

#define LDSM_X4(r0, r1, r2, r3, addr) \
    asm volatile("ldmatrix.sync.aligned.m8n8.x4.shared.b16 {%0,%1,%2,%3}, [%4];" \
        : "=r"(r0), "=r"(r1), "=r"(r2), "=r"(r3) : "r"(addr))

#define MMA16816(d, a, b) \
    asm volatile("mma.sync.aligned.m16n8k16.row.col.f32.f16.f16.f32 " \
        "{%0,%1,%2,%3}, {%4,%5,%6,%7}, {%8,%9}, {%0,%1,%2,%3};" \
        : "+f"((d)[0]), "+f"((d)[1]), "+f"((d)[2]), "+f"((d)[3]) \
        : "r"((a)[0]), "r"((a)[1]), "r"((a)[2]), "r"((a)[3]), \
          "r"((b)[0]), "r"((b)[1]))

// ---------------- fp16 store helper -----------------------------------------
__device__ __forceinline__ void store4_half(__half* p, float4 v) {
    __half2* p2 = reinterpret_cast<__half2*>(p);
    p2[0] = __floats2half2_rn(v.x, v.y);
    p2[1] = __floats2half2_rn(v.z, v.w);
}

// ---------------- weight pack: Bt[j][e], j = 4*d+g --------------------------
__global__ void pack_w_kernel(const float* __restrict__ Wa,
                              const float* __restrict__ Wb,
                              __half* __restrict__ Bo)
{
    int idx = blockIdx.x * blockDim.x + threadIdx.x;   // 1024*512
    if (idx >= N_TOT * K_HALF) return;
    int j = idx >> 9;          // 0..1023 interleaved col
    int e = idx & 511;         // 0..511
    int d = j >> 2;
    int g = j & 3;
    float v = (e < DDIM) ? Wa[g * DDIM * DDIM + e * DDIM + d]
                         : Wb[g * DDIM * DDIM + (e - DDIM) * DDIM + d];
    Bo[idx] = __float2half_rn(v);
}

__global__ void pack_bias_kernel(const float* __restrict__ b, float* __restrict__ bi)
{
    int j = blockIdx.x * blockDim.x + threadIdx.x;
    if (j >= N_TOT) return;
    bi[j] = b[(j & 3) * DDIM + (j >> 2)];
}

// ---------------- x conversion: Ax[m][0:256]=x_in, [256:512]=x_out ----------
__global__ __launch_bounds__(256) void convert_x_kernel(
    const float* __restrict__ x_in, const float* __restrict__ x_out,
    __half* __restrict__ A)
{
    int idx4 = blockIdx.x * blockDim.x + threadIdx.x;   // 8192*128
    if (idx4 >= M_TOT * 128) return;
    int m = idx4 >> 7;
    int c4 = idx4 & 127;
    float4 v = (c4 < 64)
        ? *reinterpret_cast<const float4*>(x_in + (size_t)m * DDIM + c4 * 4)
        : *reinterpret_cast<const float4*>(x_out + (size_t)m * DDIM + (c4 - 64) * 4);
    store4_half(A + (size_t)m * K_HALF + c4 * 4, v);
}

// ---------------- gather-aggregate -> fp16 packed activations --------------
__global__ __launch_bounds__(256) void gather_kernel(
    const float* __restrict__ h,
    const int*   __restrict__ in_nodes,  const float* __restrict__ in_mask,
    const int*   __restrict__ out_nodes, const float* __restrict__ out_mask,
    const float* __restrict__ node_mask,
    __half* __restrict__ A)
{
    int m  = blockIdx.x * 4 + (threadIdx.x >> 6);
    int d4 = threadIdx.x & 63;
    float nm = node_mask[m];
    __half* hin  = A + (size_t)m * K_HALF + 4 * d4;
    __half* hout = hin + DDIM;
    float4 ai = {0.f, 0.f, 0.f, 0.f};
    float4 ao = {0.f, 0.f, 0.f, 0.f};
    if (nm != 0.f) {
        const float* hb = h + (size_t)(m >> 10) * 1024 * DDIM;
        int base = m * KNBR;
        #pragma unroll
        for (int k = 0; k < KNBR; k++) {
            int   ni = in_nodes[base + k];
            float wi = in_mask [base + k];
            float4 v = *(reinterpret_cast<const float4*>(hb + (size_t)ni * DDIM) + d4);
            ai.x += wi * v.x; ai.y += wi * v.y; ai.z += wi * v.z; ai.w += wi * v.w;
            int   no = out_nodes[base + k];
            float wo = out_mask [base + k];
            float4 u = *(reinterpret_cast<const float4*>(hb + (size_t)no * DDIM) + d4);
            ao.x += wo * u.x; ao.y += wo * u.y; ao.z += wo * u.z; ao.w += wo * u.w;
        }
        ai.x *= nm; ai.y *= nm; ai.z *= nm; ai.w *= nm;
        ao.x *= nm; ao.y *= nm; ao.z *= nm; ao.w *= nm;
    }
    store4_half(hin, ai);
    store4_half(hout, ao);
}

// ---------------- HMMA GEMM + fused epilogue -------------------------------
// CTA tile 128x128, warp tile 64x32, mma.sync m16n8k16 fp16.
// K' = 512, chunks of 64, 3-stage cp.async pipeline.
// Accumulator initialized from the addend (bias / xw): those DRAM reads
// overlap the pipeline fill instead of serializing in the epilogue.
#define ABUF_SZ  (128 * 128)          // 16 KB (128 rows x 128B)
#define STAGE_SZ (2 * ABUF_SZ)        // 32 KB
#define SMEM_REQ (3 * STAGE_SZ)       // 96 KB

__device__ __forceinline__ float sigf(float x) { return 1.f / (1.f + __expf(-x)); }

// swizzled smem byte offset for (row r, 16B-granule g)
__device__ __forceinline__ uint32_t sw_off(int r, int g) {
    return (uint32_t)(r * 128 + ((g ^ (r & 7)) << 4));
}

__device__ __forceinline__ void load_chunk(
    uint32_t smA, uint32_t smB,
    const __half* A, const __half* B,
    int m0, int n0, int kc, int tid)
{
    const char* Ab = reinterpret_cast<const char*>(A) +
                     ((size_t)m0 * K_HALF + kc) * 2;
    const char* Bb = reinterpret_cast<const char*>(B) +
                     ((size_t)n0 * K_HALF + kc) * 2;
    #pragma unroll
    for (int i = 0; i < 4; i++) {
        int idx = tid + i * 256;           // 0..1023
        int r = idx >> 3;                  // 0..127
        int g = idx & 7;                   // 16B granule
        size_t go = (size_t)r * (K_HALF * 2) + g * 16;
        cp_async16(smA + sw_off(r, g), Ab + go);
        cp_async16(smB + sw_off(r, g), Bb + go);
    }
    CP_COMMIT();
}

__global__ __launch_bounds__(256, 2) void gemm_fused_kernel(
    const __half* __restrict__ A,
    const __half* __restrict__ Bmat,
    const float* __restrict__ addend,      // bias (mode0) or xw (mode1)
    const float* __restrict__ c_in, const float* __restrict__ node_mask,
    float* __restrict__ c_out, float* __restrict__ h_out,
    float* __restrict__ xw_out, int mode)
{
    extern __shared__ __align__(128) char smem_raw[];
    const uint32_t sb = smem_u32(smem_raw);
    const int tid  = threadIdx.x;
    const int wid  = tid >> 5;
    const int lane = tid & 31;
    const int m0 = blockIdx.y * 128;
    const int n0 = blockIdx.x * 128;
    const int wm = (wid >> 2) * 64;       // warp M offset (2 rows of warps)
    const int wn = (wid & 3) * 32;        // warp N offset (4 cols of warps)

    // ---- accumulator init from addend (overlaps pipeline fill) ----------
    float acc[4][4][4];
    if (mode == 0) {
        #pragma unroll
        for (int nb = 0; nb < 4; nb++) {
            int j = n0 + wn + nb * 8 + (lane & 3) * 2;
            float2 b2 = *reinterpret_cast<const float2*>(addend + j);
            #pragma unroll
            for (int mi = 0; mi < 4; mi++) {
                acc[mi][nb][0] = b2.x; acc[mi][nb][1] = b2.y;
                acc[mi][nb][2] = b2.x; acc[mi][nb][3] = b2.y;
            }
        }
    } else {
        #pragma unroll
        for (int mi = 0; mi < 4; mi++) {
            int mlo = m0 + wm + mi * 16 + (lane >> 2);
            #pragma unroll
            for (int nb = 0; nb < 4; nb++) {
                int j = n0 + wn + nb * 8 + (lane & 3) * 2;
                float2 v0 = *reinterpret_cast<const float2*>(
                    addend + (size_t)mlo * N_TOT + j);
                float2 v1 = *reinterpret_cast<const float2*>(
                    addend + (size_t)(mlo + 8) * N_TOT + j);
                acc[mi][nb][0] = v0.x; acc[mi][nb][1] = v0.y;
                acc[mi][nb][2] = v1.x; acc[mi][nb][3] = v1.y;
            }
        }
    }

    // prologue: fill stages 0, 1
    #pragma unroll
    for (int s = 0; s < 2; s++) {
        uint32_t smA = sb + s * STAGE_SZ;
        load_chunk(smA, smA + ABUF_SZ, A, Bmat, m0, n0, s * 64, tid);
    }

    const int ldrow = lane & 15;          // row within 16-row fragment
    const int ghalf = lane >> 4;          // 0/1 -> 16B granule half

    for (int c = 0; c < NCHUNKS; c++) {
        if (c < NCHUNKS - 1) { CP_WAIT1(); } else { CP_WAIT0(); }
        __syncthreads();     // stage c visible; all warps done computing c-1
        if (c + 2 < NCHUNKS) {
            int kt  = c + 2;
            uint32_t dA = sb + (kt % 3) * STAGE_SZ;
            load_chunk(dA, dA + ABUF_SZ, A, Bmat, m0, n0, kt * 64, tid);
        }
        uint32_t smA = sb + (c % 3) * STAGE_SZ;
        uint32_t smB = smA + ABUF_SZ;

        #pragma unroll
        for (int ks = 0; ks < 4; ks++) {
            uint32_t aF[4][4];
            uint32_t bF[4][2];
            int g = ks * 2 + ghalf;
            #pragma unroll
            for (int mi = 0; mi < 4; mi++) {
                int r = wm + mi * 16 + ldrow;
                LDSM_X4(aF[mi][0], aF[mi][1], aF[mi][2], aF[mi][3],
                        smA + sw_off(r, g));
            }
            #pragma unroll
            for (int nj = 0; nj < 2; nj++) {
                uint32_t r0, r1, r2, r3;
                int r = wn + nj * 16 + ldrow;
                LDSM_X4(r0, r1, r2, r3, smB + sw_off(r, g));
                bF[nj * 2 + 0][0] = r0; bF[nj * 2 + 0][1] = r2;
                bF[nj * 2 + 1][0] = r1; bF[nj * 2 + 1][1] = r3;
            }
            #pragma unroll
            for (int mi = 0; mi < 4; mi++)
                #pragma unroll
                for (int nb = 0; nb < 4; nb++)
                    MMA16816(acc[mi][nb], aF[mi], bF[nb]);
        }
    }

    // ---- epilogue (addend already folded into acc) ----------------------
    if (mode == 0) {
        #pragma unroll
        for (int mi = 0; mi < 4; mi++) {
            int mlo = m0 + wm + mi * 16 + (lane >> 2);
            #pragma unroll
            for (int nb = 0; nb < 4; nb++) {
                int j = n0 + wn + nb * 8 + (lane & 3) * 2;
                float2 v0 = {acc[mi][nb][0], acc[mi][nb][1]};
                float2 v1 = {acc[mi][nb][2], acc[mi][nb][3]};
                *reinterpret_cast<float2*>(xw_out + (size_t)mlo * N_TOT + j) = v0;
                *reinterpret_cast<float2*>(xw_out + (size_t)(mlo + 8) * N_TOT + j) = v1;
            }
        }
    } else {
        const int p = lane & 1;
        #pragma unroll
        for (int mi = 0; mi < 4; mi++) {
            int m = m0 + wm + mi * 16 + (lane >> 2) + p * 8;
            float nm = node_mask[m];
            #pragma unroll
            for (int nb = 0; nb < 4; nb++) {
                float* a = acc[mi][nb];
                float o0 = __shfl_xor_sync(0xffffffffu, a[0], 1);
                float o1 = __shfl_xor_sync(0xffffffffu, a[1], 1);
                float o2 = __shfl_xor_sync(0xffffffffu, a[2], 1);
                float o3 = __shfl_xor_sync(0xffffffffu, a[3], 1);
                int dg = ((n0 + wn + nb * 8) >> 2) + ((lane & 3) >> 1);
                float vi, vo, vf, vg;
                if (p == 0) { vi = a[0]; vo = a[1]; vf = o0; vg = o1; }
                else        { vi = o2;  vo = o3;  vf = a[2]; vg = a[3]; }
                float ig = sigf(vi);
                float og = sigf(vo);
                float fg = sigf(vf);
                float gg = tanhf(vg);
                float cv = c_in[(size_t)m * DDIM + dg];
                float cn = (fg * cv + ig * gg) * nm;
                c_out[(size_t)m * DDIM + dg] = cn;
                h_out[(size_t)m * DDIM + dg] = og * tanhf(cn) * nm;
            }
        }
    }
}

// ---------------- launch ----------------------------------------------------
extern "C" void kernel_launch(void* const* d_in, const int* in_sizes, int n_in,
                              void* d_out, int out_size)
{
    const float* h0        = (const float*)d_in[0];
    const float* c0        = (const float*)d_in[1];
    const float* x_in      = (const float*)d_in[2];
    const float* x_out     = (const float*)d_in[3];
    const float* W_in      = (const float*)d_in[4];
    const float* U_in      = (const float*)d_in[5];
    const float* W_out     = (const float*)d_in[6];
    const float* U_out     = (const float*)d_in[7];
    const float* bias      = (const float*)d_in[8];
    const float* in_mask   = (const float*)d_in[9];
    const float* out_mask  = (const float*)d_in[10];
    const float* node_mask = (const float*)d_in[11];
    const int*   in_nodes  = (const int*)d_in[12];
    const int*   out_nodes = (const int*)d_in[13];

    __half *Bw, *Bu, *Ax, *Ah;
    float *xw, *hbuf, *cbuf, *bi;
    cudaGetSymbolAddress((void**)&Bw,  g_Bw);
    cudaGetSymbolAddress((void**)&Bu,  g_Bu);
    cudaGetSymbolAddress((void**)&Ax,  g_Ax);
    cudaGetSymbolAddress((void**)&Ah,  g_Ah);
    cudaGetSymbolAddress((void**)&xw,   g_xw);
    cudaGetSymbolAddress((void**)&hbuf, g_h);
    cudaGetSymbolAddress((void**)&cbuf, g_c);
    cudaGetSymbolAddress((void**)&bi,   g_bias);

    float* out = (float*)d_out;

    static bool init_done = false;
    static cudaStream_t s2;
    static cudaEvent_t evFork, evJoin;
    if (!init_done) {
        cudaFuncSetAttribute(gemm_fused_kernel,
                             cudaFuncAttributeMaxDynamicSharedMemorySize,
                             SMEM_REQ);
        cudaStreamCreateWithFlags(&s2, cudaStreamNonBlocking);
        cudaEventCreateWithFlags(&evFork, cudaEventDisableTiming);
        cudaEventCreateWithFlags(&evJoin, cudaEventDisableTiming);
        init_done = true;
    }

    const int packBlocks = (N_TOT * K_HALF + 255) / 256;
    dim3 ggrid(N_TOT / 128, M_TOT / 128);   // (8, 64)

    // fork: side stream does packU + gather(layer0) while main stream does
    // packW + bias + convertX + the layer-invariant x@W GEMM.
    cudaEventRecord(evFork, 0);
    cudaStreamWaitEvent(s2, evFork, 0);

    pack_w_kernel<<<packBlocks, 256, 0, s2>>>(U_in, U_out, Bu);
    gather_kernel<<<M_TOT / 4, 256, 0, s2>>>(h0, in_nodes, in_mask,
                                             out_nodes, out_mask, node_mask, Ah);
    cudaEventRecord(evJoin, s2);

    pack_w_kernel<<<packBlocks, 256>>>(W_in, W_out, Bw);
    pack_bias_kernel<<<4, 256>>>(bias, bi);
    convert_x_kernel<<<(M_TOT * 128 + 255) / 256, 256>>>(x_in, x_out, Ax);
    gemm_fused_kernel<<<ggrid, 256, SMEM_REQ>>>(
        Ax, Bw, bi, nullptr, nullptr, nullptr, nullptr, xw, 0);

    cudaStreamWaitEvent(0, evJoin, 0);

    for (int layer = 0; layer < LLAYERS; layer++) {
        const float* csrc = (layer == 0) ? c0 : cbuf;
        float* hdst = (layer == LLAYERS - 1) ? out : hbuf;

        if (layer > 0) {
            gather_kernel<<<M_TOT / 4, 256>>>(hbuf, in_nodes, in_mask,
                                              out_nodes, out_mask, node_mask, Ah);
        }
        gemm_fused_kernel<<<ggrid, 256, SMEM_REQ>>>(
            Ah, Bu, xw, csrc, node_mask, cbuf, hdst, nullptr, 1);
    }
}

// round 10
// speedup vs baseline: 4.7807x; 1.2286x over previous
#include <cuda_runtime.h>
#include <cuda_fp16.h>
#include <cstdint>

// Fixed problem shape: B=8, N=1024, K=16, D=256, L=3
#define M_TOT   8192
#define DDIM    256
#define KNBR    16
#define LLAYERS 3
#define K_HALF  512          // packed activation width ([in|out] halves)
#define N_TOT   1024         // 4 gates x 256, interleaved as j = 4*d+g
#define NCHUNKS 8            // K' = 512, chunks of k=64

// ---------------- device scratch (static; no runtime alloc) ----------------
__device__ __align__(256) __half g_Bw[N_TOT * K_HALF];
__device__ __align__(256) __half g_Bu[N_TOT * K_HALF];
__device__ __align__(256) __half g_Ax[M_TOT * K_HALF];
__device__ __align__(256) __half g_Ah[M_TOT * K_HALF];
__device__ __align__(256) __half g_h16[M_TOT * DDIM];    // fp16 shadow of h
__device__ __align__(256) float g_xw[M_TOT * N_TOT];     // interleaved cols
__device__ __align__(256) float g_c[M_TOT * DDIM];
__device__ __align__(256) float g_bias[N_TOT];

// ---------------- PTX helpers ----------------------------------------------
__device__ __forceinline__ uint32_t smem_u32(const void* p) {
    uint32_t a;
    asm("{ .reg .u64 t; cvta.to.shared.u64 t, %1; cvt.u32.u64 %0, t; }"
        : "=r"(a) : "l"(p));
    return a;
}
__device__ __forceinline__ void cp_async16(uint32_t dst, const void* src) {
    asm volatile("cp.async.cg.shared.global [%0], [%1], 16;\n"
                 :: "r"(dst), "l"(src));
}
#define CP_COMMIT() asm volatile("cp.async.commit_group;" ::: "memory")
#define CP_WAIT1()  asm volatile("cp.async.wait_group 1;" ::: "memory")
#define CP_WAIT0()  asm volatile("cp.async.wait_group 0;" ::: "memory")

#define LDSM_X4(r0, r1, r2, r3, addr) \
    asm volatile("ldmatrix.sync.aligned.m8n8.x4.shared.b16 {%0,%1,%2,%3}, [%4];" \
        : "=r"(r0), "=r"(r1), "=r"(r2), "=r"(r3) : "r"(addr))

#define MMA16816(d, a, b) \
    asm volatile("mma.sync.aligned.m16n8k16.row.col.f32.f16.f16.f32 " \
        "{%0,%1,%2,%3}, {%4,%5,%6,%7}, {%8,%9}, {%0,%1,%2,%3};" \
        : "+f"((d)[0]), "+f"((d)[1]), "+f"((d)[2]), "+f"((d)[3]) \
        : "r"((a)[0]), "r"((a)[1]), "r"((a)[2]), "r"((a)[3]), \
          "r"((b)[0]), "r"((b)[1]))

// ---------------- fp16 store helper -----------------------------------------
__device__ __forceinline__ void store4_half(__half* p, float4 v) {
    __half2* p2 = reinterpret_cast<__half2*>(p);
    p2[0] = __floats2half2_rn(v.x, v.y);
    p2[1] = __floats2half2_rn(v.z, v.w);
}

// ---------------- weight pack: Bt[j][e], j = 4*d+g --------------------------
__global__ void pack_w_kernel(const float* __restrict__ Wa,
                              const float* __restrict__ Wb,
                              __half* __restrict__ Bo)
{
    int idx = blockIdx.x * blockDim.x + threadIdx.x;   // 1024*512
    if (idx >= N_TOT * K_HALF) return;
    int j = idx >> 9;          // 0..1023 interleaved col
    int e = idx & 511;         // 0..511
    int d = j >> 2;
    int g = j & 3;
    float v = (e < DDIM) ? Wa[g * DDIM * DDIM + e * DDIM + d]
                         : Wb[g * DDIM * DDIM + (e - DDIM) * DDIM + d];
    Bo[idx] = __float2half_rn(v);
}

__global__ void pack_bias_kernel(const float* __restrict__ b, float* __restrict__ bi)
{
    int j = blockIdx.x * blockDim.x + threadIdx.x;
    if (j >= N_TOT) return;
    bi[j] = b[(j & 3) * DDIM + (j >> 2)];
}

// ---------------- x conversion: Ax[m][0:256]=x_in, [256:512]=x_out ----------
__global__ __launch_bounds__(256) void convert_x_kernel(
    const float* __restrict__ x_in, const float* __restrict__ x_out,
    __half* __restrict__ A)
{
    int idx4 = blockIdx.x * blockDim.x + threadIdx.x;   // 8192*128
    if (idx4 >= M_TOT * 128) return;
    int m = idx4 >> 7;
    int c4 = idx4 & 127;
    float4 v = (c4 < 64)
        ? *reinterpret_cast<const float4*>(x_in + (size_t)m * DDIM + c4 * 4)
        : *reinterpret_cast<const float4*>(x_out + (size_t)m * DDIM + (c4 - 64) * 4);
    store4_half(A + (size_t)m * K_HALF + c4 * 4, v);
}

// ---------------- gather (fp32 h source, layer 0) ---------------------------
__global__ __launch_bounds__(256) void gather_f32_kernel(
    const float* __restrict__ h,
    const int*   __restrict__ in_nodes,  const float* __restrict__ in_mask,
    const int*   __restrict__ out_nodes, const float* __restrict__ out_mask,
    const float* __restrict__ node_mask,
    __half* __restrict__ A)
{
    int m  = blockIdx.x * 4 + (threadIdx.x >> 6);
    int d4 = threadIdx.x & 63;
    float nm = node_mask[m];
    __half* hin  = A + (size_t)m * K_HALF + 4 * d4;
    __half* hout = hin + DDIM;
    float4 ai = {0.f, 0.f, 0.f, 0.f};
    float4 ao = {0.f, 0.f, 0.f, 0.f};
    if (nm != 0.f) {
        const float* hb = h + (size_t)(m >> 10) * 1024 * DDIM;
        int base = m * KNBR;
        #pragma unroll
        for (int k = 0; k < KNBR; k++) {
            int   ni = in_nodes[base + k];
            float wi = in_mask [base + k];
            float4 v = *(reinterpret_cast<const float4*>(hb + (size_t)ni * DDIM) + d4);
            ai.x += wi * v.x; ai.y += wi * v.y; ai.z += wi * v.z; ai.w += wi * v.w;
            int   no = out_nodes[base + k];
            float wo = out_mask [base + k];
            float4 u = *(reinterpret_cast<const float4*>(hb + (size_t)no * DDIM) + d4);
            ao.x += wo * u.x; ao.y += wo * u.y; ao.z += wo * u.z; ao.w += wo * u.w;
        }
        ai.x *= nm; ai.y *= nm; ai.z *= nm; ai.w *= nm;
        ao.x *= nm; ao.y *= nm; ao.z *= nm; ao.w *= nm;
    }
    store4_half(hin, ai);
    store4_half(hout, ao);
}

// ---------------- gather (fp16 h source, layers 1..) ------------------------
__global__ __launch_bounds__(256) void gather_f16_kernel(
    const __half* __restrict__ h16,
    const int*   __restrict__ in_nodes,  const float* __restrict__ in_mask,
    const int*   __restrict__ out_nodes, const float* __restrict__ out_mask,
    const float* __restrict__ node_mask,
    __half* __restrict__ A)
{
    int m  = blockIdx.x * 4 + (threadIdx.x >> 6);
    int d4 = threadIdx.x & 63;
    float nm = node_mask[m];
    __half* hin  = A + (size_t)m * K_HALF + 4 * d4;
    __half* hout = hin + DDIM;
    float4 ai = {0.f, 0.f, 0.f, 0.f};
    float4 ao = {0.f, 0.f, 0.f, 0.f};
    if (nm != 0.f) {
        const __half* hb = h16 + (size_t)(m >> 10) * 1024 * DDIM;
        int base = m * KNBR;
        #pragma unroll
        for (int k = 0; k < KNBR; k++) {
            int   ni = in_nodes[base + k];
            float wi = in_mask [base + k];
            uint2 rv = *reinterpret_cast<const uint2*>(hb + (size_t)ni * DDIM + d4 * 4);
            float2 f0 = __half22float2(*reinterpret_cast<__half2*>(&rv.x));
            float2 f1 = __half22float2(*reinterpret_cast<__half2*>(&rv.y));
            ai.x += wi * f0.x; ai.y += wi * f0.y; ai.z += wi * f1.x; ai.w += wi * f1.y;
            int   no = out_nodes[base + k];
            float wo = out_mask [base + k];
            uint2 ru = *reinterpret_cast<const uint2*>(hb + (size_t)no * DDIM + d4 * 4);
            float2 g0 = __half22float2(*reinterpret_cast<__half2*>(&ru.x));
            float2 g1 = __half22float2(*reinterpret_cast<__half2*>(&ru.y));
            ao.x += wo * g0.x; ao.y += wo * g0.y; ao.z += wo * g1.x; ao.w += wo * g1.y;
        }
        ai.x *= nm; ai.y *= nm; ai.z *= nm; ai.w *= nm;
        ao.x *= nm; ao.y *= nm; ao.z *= nm; ao.w *= nm;
    }
    store4_half(hin, ai);
    store4_half(hout, ao);
}

// ---------------- HMMA GEMM + fused epilogue -------------------------------
// CTA tile 128x128, warp tile 64x32, mma.sync m16n8k16 fp16.
// K' = 512, chunks of 64, 3-stage cp.async pipeline; acc init from addend.
// mode 0: write xw; mode 1: intermediate layer (c fp32 + h fp16 shadow);
// mode 2: final layer (h fp32 only).
#define ABUF_SZ  (128 * 128)          // 16 KB (128 rows x 128B)
#define STAGE_SZ (2 * ABUF_SZ)        // 32 KB
#define SMEM_REQ (3 * STAGE_SZ)       // 96 KB

__device__ __forceinline__ float sigf(float x) { return 1.f / (1.f + __expf(-x)); }

// swizzled smem byte offset for (row r, 16B-granule g)
__device__ __forceinline__ uint32_t sw_off(int r, int g) {
    return (uint32_t)(r * 128 + ((g ^ (r & 7)) << 4));
}

__device__ __forceinline__ void load_chunk(
    uint32_t smA, uint32_t smB,
    const __half* A, const __half* B,
    int m0, int n0, int kc, int tid)
{
    const char* Ab = reinterpret_cast<const char*>(A) +
                     ((size_t)m0 * K_HALF + kc) * 2;
    const char* Bb = reinterpret_cast<const char*>(B) +
                     ((size_t)n0 * K_HALF + kc) * 2;
    #pragma unroll
    for (int i = 0; i < 4; i++) {
        int idx = tid + i * 256;           // 0..1023
        int r = idx >> 3;                  // 0..127
        int g = idx & 7;                   // 16B granule
        size_t go = (size_t)r * (K_HALF * 2) + g * 16;
        cp_async16(smA + sw_off(r, g), Ab + go);
        cp_async16(smB + sw_off(r, g), Bb + go);
    }
    CP_COMMIT();
}

__global__ __launch_bounds__(256, 2) void gemm_fused_kernel(
    const __half* __restrict__ A,
    const __half* __restrict__ Bmat,
    const float* __restrict__ addend,      // bias (mode0) or xw (mode1/2)
    const float* __restrict__ c_in, const float* __restrict__ node_mask,
    float* __restrict__ c_out, float* __restrict__ h_out,
    __half* __restrict__ h16_out,
    float* __restrict__ xw_out, int mode)
{
    extern __shared__ __align__(128) char smem_raw[];
    const uint32_t sb = smem_u32(smem_raw);
    const int tid  = threadIdx.x;
    const int wid  = tid >> 5;
    const int lane = tid & 31;
    const int m0 = blockIdx.y * 128;
    const int n0 = blockIdx.x * 128;
    const int wm = (wid >> 2) * 64;       // warp M offset (2 rows of warps)
    const int wn = (wid & 3) * 32;        // warp N offset (4 cols of warps)

    // ---- accumulator init from addend (overlaps pipeline fill) ----------
    float acc[4][4][4];
    if (mode == 0) {
        #pragma unroll
        for (int nb = 0; nb < 4; nb++) {
            int j = n0 + wn + nb * 8 + (lane & 3) * 2;
            float2 b2 = *reinterpret_cast<const float2*>(addend + j);
            #pragma unroll
            for (int mi = 0; mi < 4; mi++) {
                acc[mi][nb][0] = b2.x; acc[mi][nb][1] = b2.y;
                acc[mi][nb][2] = b2.x; acc[mi][nb][3] = b2.y;
            }
        }
    } else {
        #pragma unroll
        for (int mi = 0; mi < 4; mi++) {
            int mlo = m0 + wm + mi * 16 + (lane >> 2);
            #pragma unroll
            for (int nb = 0; nb < 4; nb++) {
                int j = n0 + wn + nb * 8 + (lane & 3) * 2;
                float2 v0 = *reinterpret_cast<const float2*>(
                    addend + (size_t)mlo * N_TOT + j);
                float2 v1 = *reinterpret_cast<const float2*>(
                    addend + (size_t)(mlo + 8) * N_TOT + j);
                acc[mi][nb][0] = v0.x; acc[mi][nb][1] = v0.y;
                acc[mi][nb][2] = v1.x; acc[mi][nb][3] = v1.y;
            }
        }
    }

    // prologue: fill stages 0, 1
    #pragma unroll
    for (int s = 0; s < 2; s++) {
        uint32_t smA = sb + s * STAGE_SZ;
        load_chunk(smA, smA + ABUF_SZ, A, Bmat, m0, n0, s * 64, tid);
    }

    const int ldrow = lane & 15;          // row within 16-row fragment
    const int ghalf = lane >> 4;          // 0/1 -> 16B granule half

    for (int c = 0; c < NCHUNKS; c++) {
        if (c < NCHUNKS - 1) { CP_WAIT1(); } else { CP_WAIT0(); }
        __syncthreads();     // stage c visible; all warps done computing c-1
        if (c + 2 < NCHUNKS) {
            int kt  = c + 2;
            uint32_t dA = sb + (kt % 3) * STAGE_SZ;
            load_chunk(dA, dA + ABUF_SZ, A, Bmat, m0, n0, kt * 64, tid);
        }
        uint32_t smA = sb + (c % 3) * STAGE_SZ;
        uint32_t smB = smA + ABUF_SZ;

        #pragma unroll
        for (int ks = 0; ks < 4; ks++) {
            uint32_t aF[4][4];
            uint32_t bF[4][2];
            int g = ks * 2 + ghalf;
            #pragma unroll
            for (int mi = 0; mi < 4; mi++) {
                int r = wm + mi * 16 + ldrow;
                LDSM_X4(aF[mi][0], aF[mi][1], aF[mi][2], aF[mi][3],
                        smA + sw_off(r, g));
            }
            #pragma unroll
            for (int nj = 0; nj < 2; nj++) {
                uint32_t r0, r1, r2, r3;
                int r = wn + nj * 16 + ldrow;
                LDSM_X4(r0, r1, r2, r3, smB + sw_off(r, g));
                bF[nj * 2 + 0][0] = r0; bF[nj * 2 + 0][1] = r2;
                bF[nj * 2 + 1][0] = r1; bF[nj * 2 + 1][1] = r3;
            }
            #pragma unroll
            for (int mi = 0; mi < 4; mi++)
                #pragma unroll
                for (int nb = 0; nb < 4; nb++)
                    MMA16816(acc[mi][nb], aF[mi], bF[nb]);
        }
    }

    // ---- epilogue (addend already folded into acc) ----------------------
    if (mode == 0) {
        #pragma unroll
        for (int mi = 0; mi < 4; mi++) {
            int mlo = m0 + wm + mi * 16 + (lane >> 2);
            #pragma unroll
            for (int nb = 0; nb < 4; nb++) {
                int j = n0 + wn + nb * 8 + (lane & 3) * 2;
                float2 v0 = {acc[mi][nb][0], acc[mi][nb][1]};
                float2 v1 = {acc[mi][nb][2], acc[mi][nb][3]};
                *reinterpret_cast<float2*>(xw_out + (size_t)mlo * N_TOT + j) = v0;
                *reinterpret_cast<float2*>(xw_out + (size_t)(mlo + 8) * N_TOT + j) = v1;
            }
        }
    } else {
        // SMEM-staged LSTM epilogue: coalesced c load -> scattered smem ops
        // -> coalesced writeout. Reuses the pipeline buffers.
        float* cst = reinterpret_cast<float*>(smem_raw);          // [128][33]
        float* hst = cst + 128 * 33;                              // [128][33]
        const int d0 = n0 >> 2;   // 32 d-columns covered by this N tile

        __syncthreads();   // all warps done with pipeline smem
        #pragma unroll
        for (int i = 0; i < 4; i++) {
            int idx4 = tid + i * 256;          // 0..1023
            int r = idx4 >> 3, q = idx4 & 7;
            float4 v = *reinterpret_cast<const float4*>(
                c_in + (size_t)(m0 + r) * DDIM + d0 + q * 4);
            float* pp = cst + r * 33 + q * 4;
            pp[0] = v.x; pp[1] = v.y; pp[2] = v.z; pp[3] = v.w;
        }
        __syncthreads();

        const int pr = lane & 1;
        #pragma unroll
        for (int mi = 0; mi < 4; mi++) {
            int ml = wm + mi * 16 + (lane >> 2) + pr * 8;   // local row
            float nm = node_mask[m0 + ml];
            #pragma unroll
            for (int nb = 0; nb < 4; nb++) {
                float* a = acc[mi][nb];
                float o0 = __shfl_xor_sync(0xffffffffu, a[0], 1);
                float o1 = __shfl_xor_sync(0xffffffffu, a[1], 1);
                float o2 = __shfl_xor_sync(0xffffffffu, a[2], 1);
                float o3 = __shfl_xor_sync(0xffffffffu, a[3], 1);
                int dl = ((wn + nb * 8) >> 2) + ((lane & 3) >> 1);  // local d
                float vi, vo, vf, vg;
                if (pr == 0) { vi = a[0]; vo = a[1]; vf = o0; vg = o1; }
                else         { vi = o2;  vo = o3;  vf = a[2]; vg = a[3]; }
                float ig = sigf(vi);
                float og = sigf(vo);
                float fg = sigf(vf);
                float gg = tanhf(vg);
                float cv = cst[ml * 33 + dl];
                float cn = (fg * cv + ig * gg) * nm;
                cst[ml * 33 + dl] = cn;
                hst[ml * 33 + dl] = og * tanhf(cn) * nm;
            }
        }
        __syncthreads();

        #pragma unroll
        for (int i = 0; i < 4; i++) {
            int idx4 = tid + i * 256;
            int r = idx4 >> 3, q = idx4 & 7;
            float* pc = cst + r * 33 + q * 4;
            float* ph = hst + r * 33 + q * 4;
            float4 cv = {pc[0], pc[1], pc[2], pc[3]};
            float4 hv = {ph[0], ph[1], ph[2], ph[3]};
            size_t go = (size_t)(m0 + r) * DDIM + d0 + q * 4;
            if (mode == 1) {
                *reinterpret_cast<float4*>(c_out + go) = cv;
                __half2 h01 = __floats2half2_rn(hv.x, hv.y);
                __half2 h23 = __floats2half2_rn(hv.z, hv.w);
                uint2 hp = {*reinterpret_cast<uint32_t*>(&h01),
                            *reinterpret_cast<uint32_t*>(&h23)};
                *reinterpret_cast<uint2*>(h16_out + go) = hp;
            } else {
                *reinterpret_cast<float4*>(h_out + go) = hv;
            }
        }
    }
}

// ---------------- launch ----------------------------------------------------
extern "C" void kernel_launch(void* const* d_in, const int* in_sizes, int n_in,
                              void* d_out, int out_size)
{
    const float* h0        = (const float*)d_in[0];
    const float* c0        = (const float*)d_in[1];
    const float* x_in      = (const float*)d_in[2];
    const float* x_out     = (const float*)d_in[3];
    const float* W_in      = (const float*)d_in[4];
    const float* U_in      = (const float*)d_in[5];
    const float* W_out     = (const float*)d_in[6];
    const float* U_out     = (const float*)d_in[7];
    const float* bias      = (const float*)d_in[8];
    const float* in_mask   = (const float*)d_in[9];
    const float* out_mask  = (const float*)d_in[10];
    const float* node_mask = (const float*)d_in[11];
    const int*   in_nodes  = (const int*)d_in[12];
    const int*   out_nodes = (const int*)d_in[13];

    __half *Bw, *Bu, *Ax, *Ah, *h16;
    float *xw, *cbuf, *bi;
    cudaGetSymbolAddress((void**)&Bw,  g_Bw);
    cudaGetSymbolAddress((void**)&Bu,  g_Bu);
    cudaGetSymbolAddress((void**)&Ax,  g_Ax);
    cudaGetSymbolAddress((void**)&Ah,  g_Ah);
    cudaGetSymbolAddress((void**)&h16, g_h16);
    cudaGetSymbolAddress((void**)&xw,   g_xw);
    cudaGetSymbolAddress((void**)&cbuf, g_c);
    cudaGetSymbolAddress((void**)&bi,   g_bias);

    float* out = (float*)d_out;

    static bool init_done = false;
    static cudaStream_t s2;
    static cudaEvent_t evFork, evJoin;
    if (!init_done) {
        cudaFuncSetAttribute(gemm_fused_kernel,
                             cudaFuncAttributeMaxDynamicSharedMemorySize,
                             SMEM_REQ);
        cudaStreamCreateWithFlags(&s2, cudaStreamNonBlocking);
        cudaEventCreateWithFlags(&evFork, cudaEventDisableTiming);
        cudaEventCreateWithFlags(&evJoin, cudaEventDisableTiming);
        init_done = true;
    }

    const int packBlocks = (N_TOT * K_HALF + 255) / 256;
    dim3 ggrid(N_TOT / 128, M_TOT / 128);   // (8, 64)

    // fork: side stream does packU + gather(layer0, fp32 h0) while the main
    // stream does packW + bias + convertX + the layer-invariant x@W GEMM.
    cudaEventRecord(evFork, 0);
    cudaStreamWaitEvent(s2, evFork, 0);

    pack_w_kernel<<<packBlocks, 256, 0, s2>>>(U_in, U_out, Bu);
    gather_f32_kernel<<<M_TOT / 4, 256, 0, s2>>>(h0, in_nodes, in_mask,
                                                 out_nodes, out_mask,
                                                 node_mask, Ah);
    cudaEventRecord(evJoin, s2);

    pack_w_kernel<<<packBlocks, 256>>>(W_in, W_out, Bw);
    pack_bias_kernel<<<4, 256>>>(bias, bi);
    convert_x_kernel<<<(M_TOT * 128 + 255) / 256, 256>>>(x_in, x_out, Ax);
    gemm_fused_kernel<<<ggrid, 256, SMEM_REQ>>>(
        Ax, Bw, bi, nullptr, nullptr, nullptr, nullptr, nullptr, xw, 0);

    cudaStreamWaitEvent(0, evJoin, 0);

    for (int layer = 0; layer < LLAYERS; layer++) {
        const float* csrc = (layer == 0) ? c0 : cbuf;
        int mode = (layer == LLAYERS - 1) ? 2 : 1;

        if (layer > 0) {
            gather_f16_kernel<<<M_TOT / 4, 256>>>(h16, in_nodes, in_mask,
                                                  out_nodes, out_mask,
                                                  node_mask, Ah);
        }
        gemm_fused_kernel<<<ggrid, 256, SMEM_REQ>>>(
            Ah, Bu, xw, csrc, node_mask, cbuf, out, h16, nullptr, mode);
    }
}

// round 12
// speedup vs baseline: 5.5962x; 1.1706x over previous
#include <cuda_runtime.h>
#include <cuda_fp16.h>
#include <cstdint>

// Fixed problem shape: B=8, N=1024, K=16, D=256, L=3
#define M_TOT   8192
#define DDIM    256
#define KNBR    16
#define LLAYERS 3
#define K_HALF  512          // packed activation width ([in|out] halves)
#define N_TOT   1024         // 4 gates x 256, interleaved as j = 4*d+g
#define NCHUNKS 8            // K' = 512, chunks of k=64
#define NMTILES 64           // M_TOT / 128

// ---------------- device scratch (static; no runtime alloc) ----------------
__device__ __align__(256) __half g_Bw[N_TOT * K_HALF];
__device__ __align__(256) __half g_Bu[N_TOT * K_HALF];
__device__ __align__(256) __half g_Ax[M_TOT * K_HALF];
__device__ __align__(256) __half g_Ah[M_TOT * K_HALF];
__device__ __align__(256) __half g_h16[M_TOT * DDIM];    // fp16 shadow of h
__device__ __align__(256) float g_xw[M_TOT * N_TOT];     // interleaved cols
__device__ __align__(256) float g_c[M_TOT * DDIM];
__device__ int g_act[NMTILES];                            // per-m-tile active flag

// ---------------- PTX helpers ----------------------------------------------
__device__ __forceinline__ uint32_t smem_u32(const void* p) {
    uint32_t a;
    asm("{ .reg .u64 t; cvta.to.shared.u64 t, %1; cvt.u32.u64 %0, t; }"
        : "=r"(a) : "l"(p));
    return a;
}
__device__ __forceinline__ void cp_async16(uint32_t dst, const void* src) {
    asm volatile("cp.async.cg.shared.global [%0], [%1], 16;\n"
                 :: "r"(dst), "l"(src));
}
#define CP_COMMIT() asm volatile("cp.async.commit_group;" ::: "memory")
#define CP_WAIT1()  asm volatile("cp.async.wait_group 1;" ::: "memory")
#define CP_WAIT0()  asm volatile("cp.async.wait_group 0;" ::: "memory")

#define LDSM_X4(r0, r1, r2, r3, addr) \
    asm volatile("ldmatrix.sync.aligned.m8n8.x4.shared.b16 {%0,%1,%2,%3}, [%4];" \
        : "=r"(r0), "=r"(r1), "=r"(r2), "=r"(r3) : "r"(addr))

#define MMA16816(d, a, b) \
    asm volatile("mma.sync.aligned.m16n8k16.row.col.f32.f16.f16.f32 " \
        "{%0,%1,%2,%3}, {%4,%5,%6,%7}, {%8,%9}, {%0,%1,%2,%3};" \
        : "+f"((d)[0]), "+f"((d)[1]), "+f"((d)[2]), "+f"((d)[3]) \
        : "r"((a)[0]), "r"((a)[1]), "r"((a)[2]), "r"((a)[3]), \
          "r"((b)[0]), "r"((b)[1]))

// ---------------- fp16 store helper -----------------------------------------
__device__ __forceinline__ void store4_half(__half* p, float4 v) {
    __half2* p2 = reinterpret_cast<__half2*>(p);
    p2[0] = __floats2half2_rn(v.x, v.y);
    p2[1] = __floats2half2_rn(v.z, v.w);
}

// ---------------- per-m-tile activity flags ---------------------------------
__global__ void tile_act_kernel(const float* __restrict__ nm, int* __restrict__ act)
{
    int m = blockIdx.x * 128 + threadIdx.x;
    int any = __syncthreads_or(nm[m] != 0.f);
    if (threadIdx.x == 0) act[blockIdx.x] = any;
}

// ---------------- weight pack: Bt[j][e], j = 4*d+g --------------------------
__global__ void pack_w_kernel(const float* __restrict__ Wa,
                              const float* __restrict__ Wb,
                              __half* __restrict__ Bo)
{
    int idx = blockIdx.x * blockDim.x + threadIdx.x;   // 1024*512
    if (idx >= N_TOT * K_HALF) return;
    int j = idx >> 9;          // 0..1023 interleaved col
    int e = idx & 511;         // 0..511
    int d = j >> 2;
    int g = j & 3;
    float v = (e < DDIM) ? Wa[g * DDIM * DDIM + e * DDIM + d]
                         : Wb[g * DDIM * DDIM + (e - DDIM) * DDIM + d];
    Bo[idx] = __float2half_rn(v);
}

// ---------------- x conversion: Ax[m][0:256]=x_in, [256:512]=x_out ----------
__global__ __launch_bounds__(256) void convert_x_kernel(
    const float* __restrict__ x_in, const float* __restrict__ x_out,
    __half* __restrict__ A)
{
    int idx4 = blockIdx.x * blockDim.x + threadIdx.x;   // 8192*128
    if (idx4 >= M_TOT * 128) return;
    int m = idx4 >> 7;
    int c4 = idx4 & 127;
    float4 v = (c4 < 64)
        ? *reinterpret_cast<const float4*>(x_in + (size_t)m * DDIM + c4 * 4)
        : *reinterpret_cast<const float4*>(x_out + (size_t)m * DDIM + (c4 - 64) * 4);
    store4_half(A + (size_t)m * K_HALF + c4 * 4, v);
}

// ---------------- gather (fp32 h source, layer 0) ---------------------------
__global__ __launch_bounds__(256) void gather_f32_kernel(
    const float* __restrict__ h,
    const int*   __restrict__ in_nodes,  const float* __restrict__ in_mask,
    const int*   __restrict__ out_nodes, const float* __restrict__ out_mask,
    const float* __restrict__ node_mask,
    __half* __restrict__ A)
{
    int m  = blockIdx.x * 4 + (threadIdx.x >> 6);
    int d4 = threadIdx.x & 63;
    float nm = node_mask[m];
    __half* hin  = A + (size_t)m * K_HALF + 4 * d4;
    __half* hout = hin + DDIM;
    float4 ai = {0.f, 0.f, 0.f, 0.f};
    float4 ao = {0.f, 0.f, 0.f, 0.f};
    if (nm != 0.f) {
        const float* hb = h + (size_t)(m >> 10) * 1024 * DDIM;
        int base = m * KNBR;
        #pragma unroll
        for (int k = 0; k < KNBR; k++) {
            int   ni = in_nodes[base + k];
            float wi = in_mask [base + k];
            float4 v = *(reinterpret_cast<const float4*>(hb + (size_t)ni * DDIM) + d4);
            ai.x += wi * v.x; ai.y += wi * v.y; ai.z += wi * v.z; ai.w += wi * v.w;
            int   no = out_nodes[base + k];
            float wo = out_mask [base + k];
            float4 u = *(reinterpret_cast<const float4*>(hb + (size_t)no * DDIM) + d4);
            ao.x += wo * u.x; ao.y += wo * u.y; ao.z += wo * u.z; ao.w += wo * u.w;
        }
        ai.x *= nm; ai.y *= nm; ai.z *= nm; ai.w *= nm;
        ao.x *= nm; ao.y *= nm; ao.z *= nm; ao.w *= nm;
    }
    store4_half(hin, ai);
    store4_half(hout, ao);
}

// ---------------- gather (fp16 h source, layers 1..) ------------------------
__global__ __launch_bounds__(256) void gather_f16_kernel(
    const __half* __restrict__ h16,
    const int*   __restrict__ in_nodes,  const float* __restrict__ in_mask,
    const int*   __restrict__ out_nodes, const float* __restrict__ out_mask,
    const float* __restrict__ node_mask,
    __half* __restrict__ A)
{
    int m  = blockIdx.x * 4 + (threadIdx.x >> 6);
    int d4 = threadIdx.x & 63;
    float nm = node_mask[m];
    __half* hin  = A + (size_t)m * K_HALF + 4 * d4;
    __half* hout = hin + DDIM;
    float4 ai = {0.f, 0.f, 0.f, 0.f};
    float4 ao = {0.f, 0.f, 0.f, 0.f};
    if (nm != 0.f) {
        const __half* hb = h16 + (size_t)(m >> 10) * 1024 * DDIM;
        int base = m * KNBR;
        #pragma unroll
        for (int k = 0; k < KNBR; k++) {
            int   ni = in_nodes[base + k];
            float wi = in_mask [base + k];
            uint2 rv = *reinterpret_cast<const uint2*>(hb + (size_t)ni * DDIM + d4 * 4);
            float2 f0 = __half22float2(*reinterpret_cast<__half2*>(&rv.x));
            float2 f1 = __half22float2(*reinterpret_cast<__half2*>(&rv.y));
            ai.x += wi * f0.x; ai.y += wi * f0.y; ai.z += wi * f1.x; ai.w += wi * f1.y;
            int   no = out_nodes[base + k];
            float wo = out_mask [base + k];
            uint2 ru = *reinterpret_cast<const uint2*>(hb + (size_t)no * DDIM + d4 * 4);
            float2 g0 = __half22float2(*reinterpret_cast<__half2*>(&ru.x));
            float2 g1 = __half22float2(*reinterpret_cast<__half2*>(&ru.y));
            ao.x += wo * g0.x; ao.y += wo * g0.y; ao.z += wo * g1.x; ao.w += wo * g1.y;
        }
        ai.x *= nm; ai.y *= nm; ai.z *= nm; ai.w *= nm;
        ao.x *= nm; ao.y *= nm; ao.z *= nm; ao.w *= nm;
    }
    store4_half(hin, ai);
    store4_half(hout, ao);
}

// ---------------- HMMA GEMM + fused epilogue -------------------------------
// CTA tile 128x128, warp tile 64x32, mma.sync m16n8k16 fp16.
// K' = 512, chunks of 64, 3-stage cp.async pipeline; acc init from addend.
// mode 0: write xw (bias read raw, permuted); mode 1: intermediate layer
// (c fp32 + h fp16 shadow); mode 2: final layer (h fp32 only).
// Fully-masked m-tiles early-exit (mode 0) or zero-fill outputs (modes 1/2).
#define ABUF_SZ  (128 * 128)          // 16 KB (128 rows x 128B)
#define STAGE_SZ (2 * ABUF_SZ)        // 32 KB
#define SMEM_REQ (3 * STAGE_SZ)       // 96 KB

__device__ __forceinline__ float sigf(float x) { return 1.f / (1.f + __expf(-x)); }

// swizzled smem byte offset for (row r, 16B-granule g)
__device__ __forceinline__ uint32_t sw_off(int r, int g) {
    return (uint32_t)(r * 128 + ((g ^ (r & 7)) << 4));
}

__device__ __forceinline__ void load_chunk(
    uint32_t smA, uint32_t smB,
    const __half* A, const __half* B,
    int m0, int n0, int kc, int tid)
{
    const char* Ab = reinterpret_cast<const char*>(A) +
                     ((size_t)m0 * K_HALF + kc) * 2;
    const char* Bb = reinterpret_cast<const char*>(B) +
                     ((size_t)n0 * K_HALF + kc) * 2;
    #pragma unroll
    for (int i = 0; i < 4; i++) {
        int idx = tid + i * 256;           // 0..1023
        int r = idx >> 3;                  // 0..127
        int g = idx & 7;                   // 16B granule
        size_t go = (size_t)r * (K_HALF * 2) + g * 16;
        cp_async16(smA + sw_off(r, g), Ab + go);
        cp_async16(smB + sw_off(r, g), Bb + go);
    }
    CP_COMMIT();
}

__global__ __launch_bounds__(256, 2) void gemm_fused_kernel(
    const __half* __restrict__ A,
    const __half* __restrict__ Bmat,
    const float* __restrict__ addend,      // raw bias (mode0) or xw (mode1/2)
    const float* __restrict__ c_in, const float* __restrict__ node_mask,
    const int* __restrict__ act,
    float* __restrict__ c_out, float* __restrict__ h_out,
    __half* __restrict__ h16_out,
    float* __restrict__ xw_out, int mode)
{
    extern __shared__ __align__(128) char smem_raw[];
    const uint32_t sb = smem_u32(smem_raw);
    const int tid  = threadIdx.x;
    const int wid  = tid >> 5;
    const int lane = tid & 31;
    const int m0 = blockIdx.y * 128;
    const int n0 = blockIdx.x * 128;
    const int wm = (wid >> 2) * 64;       // warp M offset (2 rows of warps)
    const int wn = (wid & 3) * 32;        // warp N offset (4 cols of warps)
    const int d0 = n0 >> 2;               // 32 d-columns covered by this N tile

    // ---- fully-masked m-tile fast path ----------------------------------
    if (act[blockIdx.y] == 0) {
        if (mode == 0) return;            // xw of masked rows is never read
        const float4 z4 = {0.f, 0.f, 0.f, 0.f};
        #pragma unroll
        for (int i = 0; i < 4; i++) {
            int idx4 = tid + i * 256;     // 0..1023 -> (row, quad)
            int r = idx4 >> 3, q = idx4 & 7;
            size_t go = (size_t)(m0 + r) * DDIM + d0 + q * 4;
            if (mode == 1) {
                *reinterpret_cast<float4*>(c_out + go) = z4;
                uint2 zh = {0u, 0u};
                *reinterpret_cast<uint2*>(h16_out + go) = zh;
            } else {
                *reinterpret_cast<float4*>(h_out + go) = z4;
            }
        }
        return;
    }

    // ---- accumulator init from addend (overlaps pipeline fill) ----------
    float acc[4][4][4];
    if (mode == 0) {
        #pragma unroll
        for (int nb = 0; nb < 4; nb++) {
            int j = n0 + wn + nb * 8 + (lane & 3) * 2;
            // raw bias layout [4][256] -> interleaved j = 4*d + g
            float b0 = addend[(j & 3) * DDIM + (j >> 2)];
            float b1 = addend[((j + 1) & 3) * DDIM + ((j + 1) >> 2)];
            #pragma unroll
            for (int mi = 0; mi < 4; mi++) {
                acc[mi][nb][0] = b0; acc[mi][nb][1] = b1;
                acc[mi][nb][2] = b0; acc[mi][nb][3] = b1;
            }
        }
    } else {
        #pragma unroll
        for (int mi = 0; mi < 4; mi++) {
            int mlo = m0 + wm + mi * 16 + (lane >> 2);
            #pragma unroll
            for (int nb = 0; nb < 4; nb++) {
                int j = n0 + wn + nb * 8 + (lane & 3) * 2;
                float2 v0 = *reinterpret_cast<const float2*>(
                    addend + (size_t)mlo * N_TOT + j);
                float2 v1 = *reinterpret_cast<const float2*>(
                    addend + (size_t)(mlo + 8) * N_TOT + j);
                acc[mi][nb][0] = v0.x; acc[mi][nb][1] = v0.y;
                acc[mi][nb][2] = v1.x; acc[mi][nb][3] = v1.y;
            }
        }
    }

    // prologue: fill stages 0, 1
    #pragma unroll
    for (int s = 0; s < 2; s++) {
        uint32_t smA = sb + s * STAGE_SZ;
        load_chunk(smA, smA + ABUF_SZ, A, Bmat, m0, n0, s * 64, tid);
    }

    const int ldrow = lane & 15;          // row within 16-row fragment
    const int ghalf = lane >> 4;          // 0/1 -> 16B granule half

    for (int c = 0; c < NCHUNKS; c++) {
        if (c < NCHUNKS - 1) { CP_WAIT1(); } else { CP_WAIT0(); }
        __syncthreads();     // stage c visible; all warps done computing c-1
        if (c + 2 < NCHUNKS) {
            int kt  = c + 2;
            uint32_t dA = sb + (kt % 3) * STAGE_SZ;
            load_chunk(dA, dA + ABUF_SZ, A, Bmat, m0, n0, kt * 64, tid);
        }
        uint32_t smA = sb + (c % 3) * STAGE_SZ;
        uint32_t smB = smA + ABUF_SZ;

        #pragma unroll
        for (int ks = 0; ks < 4; ks++) {
            uint32_t aF[4][4];
            uint32_t bF[4][2];
            int g = ks * 2 + ghalf;
            #pragma unroll
            for (int mi = 0; mi < 4; mi++) {
                int r = wm + mi * 16 + ldrow;
                LDSM_X4(aF[mi][0], aF[mi][1], aF[mi][2], aF[mi][3],
                        smA + sw_off(r, g));
            }
            #pragma unroll
            for (int nj = 0; nj < 2; nj++) {
                uint32_t r0, r1, r2, r3;
                int r = wn + nj * 16 + ldrow;
                LDSM_X4(r0, r1, r2, r3, smB + sw_off(r, g));
                bF[nj * 2 + 0][0] = r0; bF[nj * 2 + 0][1] = r2;
                bF[nj * 2 + 1][0] = r1; bF[nj * 2 + 1][1] = r3;
            }
            #pragma unroll
            for (int mi = 0; mi < 4; mi++)
                #pragma unroll
                for (int nb = 0; nb < 4; nb++)
                    MMA16816(acc[mi][nb], aF[mi], bF[nb]);
        }
    }

    // ---- epilogue (addend already folded into acc) ----------------------
    if (mode == 0) {
        #pragma unroll
        for (int mi = 0; mi < 4; mi++) {
            int mlo = m0 + wm + mi * 16 + (lane >> 2);
            #pragma unroll
            for (int nb = 0; nb < 4; nb++) {
                int j = n0 + wn + nb * 8 + (lane & 3) * 2;
                float2 v0 = {acc[mi][nb][0], acc[mi][nb][1]};
                float2 v1 = {acc[mi][nb][2], acc[mi][nb][3]};
                *reinterpret_cast<float2*>(xw_out + (size_t)mlo * N_TOT + j) = v0;
                *reinterpret_cast<float2*>(xw_out + (size_t)(mlo + 8) * N_TOT + j) = v1;
            }
        }
    } else {
        // SMEM-staged LSTM epilogue: coalesced c load -> scattered smem ops
        // -> coalesced writeout. Reuses the pipeline buffers.
        float* cst = reinterpret_cast<float*>(smem_raw);          // [128][33]
        float* hst = cst + 128 * 33;                              // [128][33]

        __syncthreads();   // all warps done with pipeline smem
        #pragma unroll
        for (int i = 0; i < 4; i++) {
            int idx4 = tid + i * 256;          // 0..1023
            int r = idx4 >> 3, q = idx4 & 7;
            float4 v = *reinterpret_cast<const float4*>(
                c_in + (size_t)(m0 + r) * DDIM + d0 + q * 4);
            float* pp = cst + r * 33 + q * 4;
            pp[0] = v.x; pp[1] = v.y; pp[2] = v.z; pp[3] = v.w;
        }
        __syncthreads();

        const int pr = lane & 1;
        #pragma unroll
        for (int mi = 0; mi < 4; mi++) {
            int ml = wm + mi * 16 + (lane >> 2) + pr * 8;   // local row
            float nm = node_mask[m0 + ml];
            #pragma unroll
            for (int nb = 0; nb < 4; nb++) {
                float* a = acc[mi][nb];
                float o0 = __shfl_xor_sync(0xffffffffu, a[0], 1);
                float o1 = __shfl_xor_sync(0xffffffffu, a[1], 1);
                float o2 = __shfl_xor_sync(0xffffffffu, a[2], 1);
                float o3 = __shfl_xor_sync(0xffffffffu, a[3], 1);
                int dl = ((wn + nb * 8) >> 2) + ((lane & 3) >> 1);  // local d
                float vi, vo, vf, vg;
                if (pr == 0) { vi = a[0]; vo = a[1]; vf = o0; vg = o1; }
                else         { vi = o2;  vo = o3;  vf = a[2]; vg = a[3]; }
                float ig = sigf(vi);
                float og = sigf(vo);
                float fg = sigf(vf);
                float gg = tanhf(vg);
                float cv = cst[ml * 33 + dl];
                float cn = (fg * cv + ig * gg) * nm;
                cst[ml * 33 + dl] = cn;
                hst[ml * 33 + dl] = og * tanhf(cn) * nm;
            }
        }
        __syncthreads();

        #pragma unroll
        for (int i = 0; i < 4; i++) {
            int idx4 = tid + i * 256;
            int r = idx4 >> 3, q = idx4 & 7;
            float* pc = cst + r * 33 + q * 4;
            float* ph = hst + r * 33 + q * 4;
            float4 cv = {pc[0], pc[1], pc[2], pc[3]};
            float4 hv = {ph[0], ph[1], ph[2], ph[3]};
            size_t go = (size_t)(m0 + r) * DDIM + d0 + q * 4;
            if (mode == 1) {
                *reinterpret_cast<float4*>(c_out + go) = cv;
                __half2 h01 = __floats2half2_rn(hv.x, hv.y);
                __half2 h23 = __floats2half2_rn(hv.z, hv.w);
                uint2 hp = {*reinterpret_cast<uint32_t*>(&h01),
                            *reinterpret_cast<uint32_t*>(&h23)};
                *reinterpret_cast<uint2*>(h16_out + go) = hp;
            } else {
                *reinterpret_cast<float4*>(h_out + go) = hv;
            }
        }
    }
}

// ---------------- launch ----------------------------------------------------
extern "C" void kernel_launch(void* const* d_in, const int* in_sizes, int n_in,
                              void* d_out, int out_size)
{
    const float* h0        = (const float*)d_in[0];
    const float* c0        = (const float*)d_in[1];
    const float* x_in      = (const float*)d_in[2];
    const float* x_out     = (const float*)d_in[3];
    const float* W_in      = (const float*)d_in[4];
    const float* U_in      = (const float*)d_in[5];
    const float* W_out     = (const float*)d_in[6];
    const float* U_out     = (const float*)d_in[7];
    const float* bias      = (const float*)d_in[8];
    const float* in_mask   = (const float*)d_in[9];
    const float* out_mask  = (const float*)d_in[10];
    const float* node_mask = (const float*)d_in[11];
    const int*   in_nodes  = (const int*)d_in[12];
    const int*   out_nodes = (const int*)d_in[13];

    __half *Bw, *Bu, *Ax, *Ah, *h16;
    float *xw, *cbuf;
    int* act;
    cudaGetSymbolAddress((void**)&Bw,  g_Bw);
    cudaGetSymbolAddress((void**)&Bu,  g_Bu);
    cudaGetSymbolAddress((void**)&Ax,  g_Ax);
    cudaGetSymbolAddress((void**)&Ah,  g_Ah);
    cudaGetSymbolAddress((void**)&h16, g_h16);
    cudaGetSymbolAddress((void**)&xw,   g_xw);
    cudaGetSymbolAddress((void**)&cbuf, g_c);
    cudaGetSymbolAddress((void**)&act,  g_act);

    float* out = (float*)d_out;

    static bool init_done = false;
    static cudaStream_t s2, s3;
    static cudaEvent_t evFork, evJoin2, evJoin3;
    if (!init_done) {
        cudaFuncSetAttribute(gemm_fused_kernel,
                             cudaFuncAttributeMaxDynamicSharedMemorySize,
                             SMEM_REQ);
        cudaStreamCreateWithFlags(&s2, cudaStreamNonBlocking);
        cudaStreamCreateWithFlags(&s3, cudaStreamNonBlocking);
        cudaEventCreateWithFlags(&evFork, cudaEventDisableTiming);
        cudaEventCreateWithFlags(&evJoin2, cudaEventDisableTiming);
        cudaEventCreateWithFlags(&evJoin3, cudaEventDisableTiming);
        init_done = true;
    }

    const int packBlocks = (N_TOT * K_HALF + 255) / 256;
    dim3 ggrid(N_TOT / 128, M_TOT / 128);   // (8, 64)

    // fork: s2 does packU + gather(layer0, fp32 h0); s3 converts x; main
    // stream does tile flags + packW + the layer-invariant x@W GEMM.
    cudaEventRecord(evFork, 0);
    cudaStreamWaitEvent(s2, evFork, 0);
    cudaStreamWaitEvent(s3, evFork, 0);

    pack_w_kernel<<<packBlocks, 256, 0, s2>>>(U_in, U_out, Bu);
    gather_f32_kernel<<<M_TOT / 4, 256, 0, s2>>>(h0, in_nodes, in_mask,
                                                 out_nodes, out_mask,
                                                 node_mask, Ah);
    cudaEventRecord(evJoin2, s2);

    convert_x_kernel<<<(M_TOT * 128 + 255) / 256, 256, 0, s3>>>(x_in, x_out, Ax);
    cudaEventRecord(evJoin3, s3);

    tile_act_kernel<<<NMTILES, 128>>>(node_mask, act);
    pack_w_kernel<<<packBlocks, 256>>>(W_in, W_out, Bw);
    cudaStreamWaitEvent(0, evJoin3, 0);
    gemm_fused_kernel<<<ggrid, 256, SMEM_REQ>>>(
        Ax, Bw, bias, nullptr, node_mask, act,
        nullptr, nullptr, nullptr, xw, 0);

    cudaStreamWaitEvent(0, evJoin2, 0);

    for (int layer = 0; layer < LLAYERS; layer++) {
        const float* csrc = (layer == 0) ? c0 : cbuf;
        int mode = (layer == LLAYERS - 1) ? 2 : 1;

        if (layer > 0) {
            gather_f16_kernel<<<M_TOT / 4, 256>>>(h16, in_nodes, in_mask,
                                                  out_nodes, out_mask,
                                                  node_mask, Ah);
        }
        gemm_fused_kernel<<<ggrid, 256, SMEM_REQ>>>(
            Ah, Bu, xw, csrc, node_mask, act,
            cbuf, out, h16, nullptr, mode);
    }
}

// round 17
// speedup vs baseline: 5.7951x; 1.0356x over previous
#include <cuda_runtime.h>
#include <cuda_fp16.h>
#include <cstdint>

// Fixed problem shape: B=8, N=1024, K=16, D=256, L=3
#define M_TOT   8192
#define DDIM    256
#define KNBR    16
#define LLAYERS 3
#define K_HALF  512          // packed activation width ([in|out] halves)
#define N_TOT   1024         // 4 gates x 256, interleaved as j = 4*d+g
#define NCHUNKS 8            // K' = 512, chunks of k=64
#define NMTILES 64           // M_TOT / 128

// ---------------- device scratch (static; no runtime alloc) ----------------
__device__ __align__(256) __half g_Bw[N_TOT * K_HALF];
__device__ __align__(256) __half g_Bu[N_TOT * K_HALF];
__device__ __align__(256) __half g_Ax[M_TOT * K_HALF];
__device__ __align__(256) __half g_Ah[M_TOT * K_HALF];
__device__ __align__(256) __half g_h16[M_TOT * DDIM];    // fp16 shadow of h
__device__ __align__(256) float g_xw[M_TOT * N_TOT];     // interleaved cols
__device__ __align__(256) float g_c[M_TOT * DDIM];
__device__ int g_act[NMTILES];                            // per-m-tile active flag

// ---------------- PTX helpers ----------------------------------------------
__device__ __forceinline__ uint32_t smem_u32(const void* p) {
    uint32_t a;
    asm("{ .reg .u64 t; cvta.to.shared.u64 t, %1; cvt.u32.u64 %0, t; }"
        : "=r"(a) : "l"(p));
    return a;
}
__device__ __forceinline__ void cp_async16(uint32_t dst, const void* src) {
    asm volatile("cp.async.cg.shared.global [%0], [%1], 16;\n"
                 :: "r"(dst), "l"(src));
}
#define CP_COMMIT() asm volatile("cp.async.commit_group;" ::: "memory")
#define CP_WAIT1()  asm volatile("cp.async.wait_group 1;" ::: "memory")
#define CP_WAIT0()  asm volatile("cp.async.wait_group 0;" ::: "memory")

#define LDSM_X4(r0, r1, r2, r3, addr) \
    asm volatile("ldmatrix.sync.aligned.m8n8.x4.shared.b16 {%0,%1,%2,%3}, [%4];" \
        : "=r"(r0), "=r"(r1), "=r"(r2), "=r"(r3) : "r"(addr))

#define MMA16816(d, a, b) \
    asm volatile("mma.sync.aligned.m16n8k16.row.col.f32.f16.f16.f32 " \
        "{%0,%1,%2,%3}, {%4,%5,%6,%7}, {%8,%9}, {%0,%1,%2,%3};" \
        : "+f"((d)[0]), "+f"((d)[1]), "+f"((d)[2]), "+f"((d)[3]) \
        : "r"((a)[0]), "r"((a)[1]), "r"((a)[2]), "r"((a)[3]), \
          "r"((b)[0]), "r"((b)[1]))

// ---------------- fp16 store helper -----------------------------------------
__device__ __forceinline__ void store4_half(__half* p, float4 v) {
    __half2* p2 = reinterpret_cast<__half2*>(p);
    p2[0] = __floats2half2_rn(v.x, v.y);
    p2[1] = __floats2half2_rn(v.z, v.w);
}

// ---------------- per-m-tile activity flags ---------------------------------
__global__ void tile_act_kernel(const float* __restrict__ nm, int* __restrict__ act)
{
    int m = blockIdx.x * 128 + threadIdx.x;
    int any = __syncthreads_or(nm[m] != 0.f);
    if (threadIdx.x == 0) act[blockIdx.x] = any;
}

// ---------------- weight pack: Bt[j][e], j = 4*d+g --------------------------
__global__ void pack_w_kernel(const float* __restrict__ Wa,
                              const float* __restrict__ Wb,
                              __half* __restrict__ Bo)
{
    int idx = blockIdx.x * blockDim.x + threadIdx.x;   // 1024*512
    if (idx >= N_TOT * K_HALF) return;
    int j = idx >> 9;          // 0..1023 interleaved col
    int e = idx & 511;         // 0..511
    int d = j >> 2;
    int g = j & 3;
    float v = (e < DDIM) ? Wa[g * DDIM * DDIM + e * DDIM + d]
                         : Wb[g * DDIM * DDIM + (e - DDIM) * DDIM + d];
    Bo[idx] = __float2half_rn(v);
}

// ---------------- x conversion: Ax[m][0:256]=x_in, [256:512]=x_out ----------
__global__ __launch_bounds__(256) void convert_x_kernel(
    const float* __restrict__ x_in, const float* __restrict__ x_out,
    __half* __restrict__ A)
{
    int idx4 = blockIdx.x * blockDim.x + threadIdx.x;   // 8192*128
    if (idx4 >= M_TOT * 128) return;
    int m = idx4 >> 7;
    int c4 = idx4 & 127;
    float4 v = (c4 < 64)
        ? *reinterpret_cast<const float4*>(x_in + (size_t)m * DDIM + c4 * 4)
        : *reinterpret_cast<const float4*>(x_out + (size_t)m * DDIM + (c4 - 64) * 4);
    store4_half(A + (size_t)m * K_HALF + c4 * 4, v);
}

// ---------------- gather (fp32 h source, layer 0) ---------------------------
// Skips neighbor loads whose edge weight is 0 (~half of them).
__global__ __launch_bounds__(256) void gather_f32_kernel(
    const float* __restrict__ h,
    const int*   __restrict__ in_nodes,  const float* __restrict__ in_mask,
    const int*   __restrict__ out_nodes, const float* __restrict__ out_mask,
    const float* __restrict__ node_mask,
    __half* __restrict__ A)
{
    int m  = blockIdx.x * 4 + (threadIdx.x >> 6);
    int d4 = threadIdx.x & 63;
    float nm = node_mask[m];
    __half* hin  = A + (size_t)m * K_HALF + 4 * d4;
    __half* hout = hin + DDIM;
    float4 ai = {0.f, 0.f, 0.f, 0.f};
    float4 ao = {0.f, 0.f, 0.f, 0.f};
    if (nm != 0.f) {
        const float* hb = h + (size_t)(m >> 10) * 1024 * DDIM;
        int base = m * KNBR;
        #pragma unroll
        for (int k = 0; k < KNBR; k++) {
            float wi = in_mask[base + k];
            if (wi != 0.f) {
                int ni = in_nodes[base + k];
                float4 v = *(reinterpret_cast<const float4*>(hb + (size_t)ni * DDIM) + d4);
                ai.x += wi * v.x; ai.y += wi * v.y; ai.z += wi * v.z; ai.w += wi * v.w;
            }
            float wo = out_mask[base + k];
            if (wo != 0.f) {
                int no = out_nodes[base + k];
                float4 u = *(reinterpret_cast<const float4*>(hb + (size_t)no * DDIM) + d4);
                ao.x += wo * u.x; ao.y += wo * u.y; ao.z += wo * u.z; ao.w += wo * u.w;
            }
        }
        ai.x *= nm; ai.y *= nm; ai.z *= nm; ai.w *= nm;
        ao.x *= nm; ao.y *= nm; ao.z *= nm; ao.w *= nm;
    }
    store4_half(hin, ai);
    store4_half(hout, ao);
}

// ---------------- gather (fp16 h source, layers 1..) ------------------------
__global__ __launch_bounds__(256) void gather_f16_kernel(
    const __half* __restrict__ h16,
    const int*   __restrict__ in_nodes,  const float* __restrict__ in_mask,
    const int*   __restrict__ out_nodes, const float* __restrict__ out_mask,
    const float* __restrict__ node_mask,
    __half* __restrict__ A)
{
    int m  = blockIdx.x * 4 + (threadIdx.x >> 6);
    int d4 = threadIdx.x & 63;
    float nm = node_mask[m];
    __half* hin  = A + (size_t)m * K_HALF + 4 * d4;
    __half* hout = hin + DDIM;
    float4 ai = {0.f, 0.f, 0.f, 0.f};
    float4 ao = {0.f, 0.f, 0.f, 0.f};
    if (nm != 0.f) {
        const __half* hb = h16 + (size_t)(m >> 10) * 1024 * DDIM;
        int base = m * KNBR;
        #pragma unroll
        for (int k = 0; k < KNBR; k++) {
            float wi = in_mask[base + k];
            if (wi != 0.f) {
                int ni = in_nodes[base + k];
                uint2 rv = *reinterpret_cast<const uint2*>(hb + (size_t)ni * DDIM + d4 * 4);
                float2 f0 = __half22float2(*reinterpret_cast<__half2*>(&rv.x));
                float2 f1 = __half22float2(*reinterpret_cast<__half2*>(&rv.y));
                ai.x += wi * f0.x; ai.y += wi * f0.y; ai.z += wi * f1.x; ai.w += wi * f1.y;
            }
            float wo = out_mask[base + k];
            if (wo != 0.f) {
                int no = out_nodes[base + k];
                uint2 ru = *reinterpret_cast<const uint2*>(hb + (size_t)no * DDIM + d4 * 4);
                float2 g0 = __half22float2(*reinterpret_cast<__half2*>(&ru.x));
                float2 g1 = __half22float2(*reinterpret_cast<__half2*>(&ru.y));
                ao.x += wo * g0.x; ao.y += wo * g0.y; ao.z += wo * g1.x; ao.w += wo * g1.y;
            }
        }
        ai.x *= nm; ai.y *= nm; ai.z *= nm; ai.w *= nm;
        ao.x *= nm; ao.y *= nm; ao.z *= nm; ao.w *= nm;
    }
    store4_half(hin, ai);
    store4_half(hout, ao);
}

// ---------------- HMMA GEMM + fused epilogue -------------------------------
// CTA tile 128x128, warp tile 64x32, mma.sync m16n8k16 fp16.
// K' = 512, chunks of 64, 3-stage cp.async pipeline; acc init from addend.
// mode 0: write xw (bias read raw, permuted); mode 1: intermediate layer
// (c fp32 + h fp16 shadow); mode 2: final layer (h fp32 only).
// Fully-masked m-tiles early-exit (mode 0) or zero-fill outputs (modes 1/2).
#define ABUF_SZ  (128 * 128)          // 16 KB (128 rows x 128B)
#define STAGE_SZ (2 * ABUF_SZ)        // 32 KB
#define SMEM_REQ (3 * STAGE_SZ)       // 96 KB

__device__ __forceinline__ float sigf(float x) { return 1.f / (1.f + __expf(-x)); }

// swizzled smem byte offset for (row r, 16B-granule g)
__device__ __forceinline__ uint32_t sw_off(int r, int g) {
    return (uint32_t)(r * 128 + ((g ^ (r & 7)) << 4));
}

__device__ __forceinline__ void load_chunk(
    uint32_t smA, uint32_t smB,
    const __half* A, const __half* B,
    int m0, int n0, int kc, int tid)
{
    const char* Ab = reinterpret_cast<const char*>(A) +
                     ((size_t)m0 * K_HALF + kc) * 2;
    const char* Bb = reinterpret_cast<const char*>(B) +
                     ((size_t)n0 * K_HALF + kc) * 2;
    #pragma unroll
    for (int i = 0; i < 4; i++) {
        int idx = tid + i * 256;           // 0..1023
        int r = idx >> 3;                  // 0..127
        int g = idx & 7;                   // 16B granule
        size_t go = (size_t)r * (K_HALF * 2) + g * 16;
        cp_async16(smA + sw_off(r, g), Ab + go);
        cp_async16(smB + sw_off(r, g), Bb + go);
    }
    CP_COMMIT();
}

__global__ __launch_bounds__(256, 2) void gemm_fused_kernel(
    const __half* __restrict__ A,
    const __half* __restrict__ Bmat,
    const float* __restrict__ addend,      // raw bias (mode0) or xw (mode1/2)
    const float* __restrict__ c_in, const float* __restrict__ node_mask,
    const int* __restrict__ act,
    float* __restrict__ c_out, float* __restrict__ h_out,
    __half* __restrict__ h16_out,
    float* __restrict__ xw_out, int mode)
{
    extern __shared__ __align__(128) char smem_raw[];
    const uint32_t sb = smem_u32(smem_raw);
    const int tid  = threadIdx.x;
    const int wid  = tid >> 5;
    const int lane = tid & 31;
    const int m0 = blockIdx.y * 128;
    const int n0 = blockIdx.x * 128;
    const int wm = (wid >> 2) * 64;       // warp M offset (2 rows of warps)
    const int wn = (wid & 3) * 32;        // warp N offset (4 cols of warps)
    const int d0 = n0 >> 2;               // 32 d-columns covered by this N tile

    // ---- fully-masked m-tile fast path ----------------------------------
    if (act[blockIdx.y] == 0) {
        if (mode == 0) return;            // xw of masked rows is never read
        const float4 z4 = {0.f, 0.f, 0.f, 0.f};
        #pragma unroll
        for (int i = 0; i < 4; i++) {
            int idx4 = tid + i * 256;     // 0..1023 -> (row, quad)
            int r = idx4 >> 3, q = idx4 & 7;
            size_t go = (size_t)(m0 + r) * DDIM + d0 + q * 4;
            if (mode == 1) {
                *reinterpret_cast<float4*>(c_out + go) = z4;
                uint2 zh = {0u, 0u};
                *reinterpret_cast<uint2*>(h16_out + go) = zh;
            } else {
                *reinterpret_cast<float4*>(h_out + go) = z4;
            }
        }
        return;
    }

    // ---- accumulator init from addend (overlaps pipeline fill) ----------
    float acc[4][4][4];
    if (mode == 0) {
        #pragma unroll
        for (int nb = 0; nb < 4; nb++) {
            int j = n0 + wn + nb * 8 + (lane & 3) * 2;
            // raw bias layout [4][256] -> interleaved j = 4*d + g
            float b0 = addend[(j & 3) * DDIM + (j >> 2)];
            float b1 = addend[((j + 1) & 3) * DDIM + ((j + 1) >> 2)];
            #pragma unroll
            for (int mi = 0; mi < 4; mi++) {
                acc[mi][nb][0] = b0; acc[mi][nb][1] = b1;
                acc[mi][nb][2] = b0; acc[mi][nb][3] = b1;
            }
        }
    } else {
        #pragma unroll
        for (int mi = 0; mi < 4; mi++) {
            int mlo = m0 + wm + mi * 16 + (lane >> 2);
            #pragma unroll
            for (int nb = 0; nb < 4; nb++) {
                int j = n0 + wn + nb * 8 + (lane & 3) * 2;
                float2 v0 = *reinterpret_cast<const float2*>(
                    addend + (size_t)mlo * N_TOT + j);
                float2 v1 = *reinterpret_cast<const float2*>(
                    addend + (size_t)(mlo + 8) * N_TOT + j);
                acc[mi][nb][0] = v0.x; acc[mi][nb][1] = v0.y;
                acc[mi][nb][2] = v1.x; acc[mi][nb][3] = v1.y;
            }
        }
    }

    // prologue: fill stages 0, 1
    #pragma unroll
    for (int s = 0; s < 2; s++) {
        uint32_t smA = sb + s * STAGE_SZ;
        load_chunk(smA, smA + ABUF_SZ, A, Bmat, m0, n0, s * 64, tid);
    }

    const int ldrow = lane & 15;          // row within 16-row fragment
    const int ghalf = lane >> 4;          // 0/1 -> 16B granule half

    for (int c = 0; c < NCHUNKS; c++) {
        if (c < NCHUNKS - 1) { CP_WAIT1(); } else { CP_WAIT0(); }
        __syncthreads();     // stage c visible; all warps done computing c-1
        if (c + 2 < NCHUNKS) {
            int kt  = c + 2;
            uint32_t dA = sb + (kt % 3) * STAGE_SZ;
            load_chunk(dA, dA + ABUF_SZ, A, Bmat, m0, n0, kt * 64, tid);
        }
        uint32_t smA = sb + (c % 3) * STAGE_SZ;
        uint32_t smB = smA + ABUF_SZ;

        #pragma unroll
        for (int ks = 0; ks < 4; ks++) {
            uint32_t aF[4][4];
            uint32_t bF[4][2];
            int g = ks * 2 + ghalf;
            #pragma unroll
            for (int mi = 0; mi < 4; mi++) {
                int r = wm + mi * 16 + ldrow;
                LDSM_X4(aF[mi][0], aF[mi][1], aF[mi][2], aF[mi][3],
                        smA + sw_off(r, g));
            }
            #pragma unroll
            for (int nj = 0; nj < 2; nj++) {
                uint32_t r0, r1, r2, r3;
                int r = wn + nj * 16 + ldrow;
                LDSM_X4(r0, r1, r2, r3, smB + sw_off(r, g));
                bF[nj * 2 + 0][0] = r0; bF[nj * 2 + 0][1] = r2;
                bF[nj * 2 + 1][0] = r1; bF[nj * 2 + 1][1] = r3;
            }
            #pragma unroll
            for (int mi = 0; mi < 4; mi++)
                #pragma unroll
                for (int nb = 0; nb < 4; nb++)
                    MMA16816(acc[mi][nb], aF[mi], bF[nb]);
        }
    }

    // ---- epilogue (addend already folded into acc) ----------------------
    if (mode == 0) {
        #pragma unroll
        for (int mi = 0; mi < 4; mi++) {
            int mlo = m0 + wm + mi * 16 + (lane >> 2);
            #pragma unroll
            for (int nb = 0; nb < 4; nb++) {
                int j = n0 + wn + nb * 8 + (lane & 3) * 2;
                float2 v0 = {acc[mi][nb][0], acc[mi][nb][1]};
                float2 v1 = {acc[mi][nb][2], acc[mi][nb][3]};
                *reinterpret_cast<float2*>(xw_out + (size_t)mlo * N_TOT + j) = v0;
                *reinterpret_cast<float2*>(xw_out + (size_t)(mlo + 8) * N_TOT + j) = v1;
            }
        }
    } else {
        // SMEM-staged LSTM epilogue: coalesced c load -> scattered smem ops
        // -> coalesced writeout. Reuses the pipeline buffers.
        float* cst = reinterpret_cast<float*>(smem_raw);          // [128][33]
        float* hst = cst + 128 * 33;                              // [128][33]

        __syncthreads();   // all warps done with pipeline smem
        #pragma unroll
        for (int i = 0; i < 4; i++) {
            int idx4 = tid + i * 256;          // 0..1023
            int r = idx4 >> 3, q = idx4 & 7;
            float4 v = *reinterpret_cast<const float4*>(
                c_in + (size_t)(m0 + r) * DDIM + d0 + q * 4);
            float* pp = cst + r * 33 + q * 4;
            pp[0] = v.x; pp[1] = v.y; pp[2] = v.z; pp[3] = v.w;
        }
        __syncthreads();

        const int pr = lane & 1;
        #pragma unroll
        for (int mi = 0; mi < 4; mi++) {
            int ml = wm + mi * 16 + (lane >> 2) + pr * 8;   // local row
            float nm = node_mask[m0 + ml];
            #pragma unroll
            for (int nb = 0; nb < 4; nb++) {
                float* a = acc[mi][nb];
                float o0 = __shfl_xor_sync(0xffffffffu, a[0], 1);
                float o1 = __shfl_xor_sync(0xffffffffu, a[1], 1);
                float o2 = __shfl_xor_sync(0xffffffffu, a[2], 1);
                float o3 = __shfl_xor_sync(0xffffffffu, a[3], 1);
                int dl = ((wn + nb * 8) >> 2) + ((lane & 3) >> 1);  // local d
                float vi, vo, vf, vg;
                if (pr == 0) { vi = a[0]; vo = a[1]; vf = o0; vg = o1; }
                else         { vi = o2;  vo = o3;  vf = a[2]; vg = a[3]; }
                float ig = sigf(vi);
                float og = sigf(vo);
                float fg = sigf(vf);
                float gg = tanhf(vg);
                float cv = cst[ml * 33 + dl];
                float cn = (fg * cv + ig * gg) * nm;
                cst[ml * 33 + dl] = cn;
                hst[ml * 33 + dl] = og * tanhf(cn) * nm;
            }
        }
        __syncthreads();

        #pragma unroll
        for (int i = 0; i < 4; i++) {
            int idx4 = tid + i * 256;
            int r = idx4 >> 3, q = idx4 & 7;
            float* pc = cst + r * 33 + q * 4;
            float* ph = hst + r * 33 + q * 4;
            float4 cv = {pc[0], pc[1], pc[2], pc[3]};
            float4 hv = {ph[0], ph[1], ph[2], ph[3]};
            size_t go = (size_t)(m0 + r) * DDIM + d0 + q * 4;
            if (mode == 1) {
                *reinterpret_cast<float4*>(c_out + go) = cv;
                __half2 h01 = __floats2half2_rn(hv.x, hv.y);
                __half2 h23 = __floats2half2_rn(hv.z, hv.w);
                uint2 hp = {*reinterpret_cast<uint32_t*>(&h01),
                            *reinterpret_cast<uint32_t*>(&h23)};
                *reinterpret_cast<uint2*>(h16_out + go) = hp;
            } else {
                *reinterpret_cast<float4*>(h_out + go) = hv;
            }
        }
    }
}

// ---------------- launch ----------------------------------------------------
extern "C" void kernel_launch(void* const* d_in, const int* in_sizes, int n_in,
                              void* d_out, int out_size)
{
    const float* h0        = (const float*)d_in[0];
    const float* c0        = (const float*)d_in[1];
    const float* x_in      = (const float*)d_in[2];
    const float* x_out     = (const float*)d_in[3];
    const float* W_in      = (const float*)d_in[4];
    const float* U_in      = (const float*)d_in[5];
    const float* W_out     = (const float*)d_in[6];
    const float* U_out     = (const float*)d_in[7];
    const float* bias      = (const float*)d_in[8];
    const float* in_mask   = (const float*)d_in[9];
    const float* out_mask  = (const float*)d_in[10];
    const float* node_mask = (const float*)d_in[11];
    const int*   in_nodes  = (const int*)d_in[12];
    const int*   out_nodes = (const int*)d_in[13];

    __half *Bw, *Bu, *Ax, *Ah, *h16;
    float *xw, *cbuf;
    int* act;
    cudaGetSymbolAddress((void**)&Bw,  g_Bw);
    cudaGetSymbolAddress((void**)&Bu,  g_Bu);
    cudaGetSymbolAddress((void**)&Ax,  g_Ax);
    cudaGetSymbolAddress((void**)&Ah,  g_Ah);
    cudaGetSymbolAddress((void**)&h16, g_h16);
    cudaGetSymbolAddress((void**)&xw,   g_xw);
    cudaGetSymbolAddress((void**)&cbuf, g_c);
    cudaGetSymbolAddress((void**)&act,  g_act);

    float* out = (float*)d_out;

    static bool init_done = false;
    static cudaStream_t s2, s3;
    static cudaEvent_t evFork, evJoin2, evJoin3;
    if (!init_done) {
        cudaFuncSetAttribute(gemm_fused_kernel,
                             cudaFuncAttributeMaxDynamicSharedMemorySize,
                             SMEM_REQ);
        cudaStreamCreateWithFlags(&s2, cudaStreamNonBlocking);
        cudaStreamCreateWithFlags(&s3, cudaStreamNonBlocking);
        cudaEventCreateWithFlags(&evFork, cudaEventDisableTiming);
        cudaEventCreateWithFlags(&evJoin2, cudaEventDisableTiming);
        cudaEventCreateWithFlags(&evJoin3, cudaEventDisableTiming);
        init_done = true;
    }

    const int packBlocks = (N_TOT * K_HALF + 255) / 256;
    dim3 ggrid(N_TOT / 128, M_TOT / 128);   // (8, 64)

    // fork: s2 does packU + gather(layer0, fp32 h0); s3 converts x and
    // computes tile flags; main stream does packW + the x@W GEMM.
    cudaEventRecord(evFork, 0);
    cudaStreamWaitEvent(s2, evFork, 0);
    cudaStreamWaitEvent(s3, evFork, 0);

    pack_w_kernel<<<packBlocks, 256, 0, s2>>>(U_in, U_out, Bu);
    gather_f32_kernel<<<M_TOT / 4, 256, 0, s2>>>(h0, in_nodes, in_mask,
                                                 out_nodes, out_mask,
                                                 node_mask, Ah);
    cudaEventRecord(evJoin2, s2);

    convert_x_kernel<<<(M_TOT * 128 + 255) / 256, 256, 0, s3>>>(x_in, x_out, Ax);
    tile_act_kernel<<<NMTILES, 128, 0, s3>>>(node_mask, act);
    cudaEventRecord(evJoin3, s3);

    pack_w_kernel<<<packBlocks, 256>>>(W_in, W_out, Bw);
    cudaStreamWaitEvent(0, evJoin3, 0);
    gemm_fused_kernel<<<ggrid, 256, SMEM_REQ>>>(
        Ax, Bw, bias, nullptr, node_mask, act,
        nullptr, nullptr, nullptr, xw, 0);

    cudaStreamWaitEvent(0, evJoin2, 0);

    for (int layer = 0; layer < LLAYERS; layer++) {
        const float* csrc = (layer == 0) ? c0 : cbuf;
        int mode = (layer == LLAYERS - 1) ? 2 : 1;

        if (layer > 0) {
            gather_f16_kernel<<<M_TOT / 4, 256>>>(h16, in_nodes, in_mask,
                                                  out_nodes, out_mask,
                                                  node_mask, Ah);
        }
        gemm_fused_kernel<<<ggrid, 256, SMEM_REQ>>>(
            Ah, Bu, xw, csrc, node_mask, act,
            cbuf, out, h16, nullptr, mode);
    }
}